// round 1
// baseline (speedup 1.0000x reference)
#include <cuda_runtime.h>

// Problem constants
#define BATCH 32
#define CH    512
#define NPIX  1024   // H*W = 32*32
#define NGRP  32
#define CPG   16     // channels per group

// ---------------------------------------------------------------------------
// Scratch (device globals — no allocations allowed)
// ---------------------------------------------------------------------------
__device__ float g_mean[BATCH * NGRP];
__device__ float g_rstd[BATCH * NGRP];
__device__ float g_h   [(size_t)BATCH * CH * NPIX];        //  64 MiB
__device__ float g_qkv [(size_t)BATCH * 3 * CH * NPIX];    // 192 MiB
__device__ float g_attn[(size_t)BATCH * NPIX * NPIX];      // 128 MiB
__device__ float g_hout[(size_t)BATCH * CH * NPIX];        //  64 MiB

// ---------------------------------------------------------------------------
// Helpers
// ---------------------------------------------------------------------------
__device__ __forceinline__ float warp_sum(float v) {
    #pragma unroll
    for (int o = 16; o; o >>= 1) v += __shfl_xor_sync(0xffffffffu, v, o);
    return v;
}
__device__ __forceinline__ float warp_max(float v) {
    #pragma unroll
    for (int o = 16; o; o >>= 1) v = fmaxf(v, __shfl_xor_sync(0xffffffffu, v, o));
    return v;
}

// Packed fp32x2 FMA (sm_103a: scalar FFMA-3reg is half-rate; FFMA2 only via PTX)
__device__ __forceinline__ unsigned long long pk2(float lo, float hi) {
    unsigned long long r;
    asm("mov.b64 %0, {%1, %2};" : "=l"(r) : "f"(lo), "f"(hi));
    return r;
}
__device__ __forceinline__ void fma2(unsigned long long& d,
                                     unsigned long long a,
                                     unsigned long long b) {
    asm("fma.rn.f32x2 %0, %1, %2, %3;" : "=l"(d) : "l"(a), "l"(b), "l"(d));
}
__device__ __forceinline__ float2 up2(unsigned long long v) {
    float2 r;
    asm("mov.b64 {%0, %1}, %2;" : "=f"(r.x), "=f"(r.y) : "l"(v));
    return r;
}

// ---------------------------------------------------------------------------
// GroupNorm stats: one block per (batch, group). Group slab is contiguous
// (16 channels * 1024 pixels = 16384 floats).
// ---------------------------------------------------------------------------
__global__ void gn_stats_k(const float* __restrict__ x) {
    const int bg = blockIdx.x;                       // b*32 + g
    const float4* p = (const float4*)(x + (size_t)bg * (CPG * NPIX));
    float s = 0.f, ss = 0.f;
    for (int i = threadIdx.x; i < (CPG * NPIX) / 4; i += 256) {
        float4 v = p[i];
        s  += v.x + v.y + v.z + v.w;
        ss += v.x * v.x + v.y * v.y + v.z * v.z + v.w * v.w;
    }
    __shared__ float sh1[8], sh2[8];
    s = warp_sum(s); ss = warp_sum(ss);
    const int w = threadIdx.x >> 5, l = threadIdx.x & 31;
    if (!l) { sh1[w] = s; sh2[w] = ss; }
    __syncthreads();
    if (threadIdx.x < 32) {
        float a = (threadIdx.x < 8) ? sh1[threadIdx.x] : 0.f;
        float b = (threadIdx.x < 8) ? sh2[threadIdx.x] : 0.f;
        a = warp_sum(a); b = warp_sum(b);
        if (!threadIdx.x) {
            const float inv_n = 1.f / (float)(CPG * NPIX);
            float m   = a * inv_n;
            float var = b * inv_n - m * m;
            g_mean[bg] = m;
            g_rstd[bg] = rsqrtf(var + 1e-5f);
        }
    }
}

// Apply norm: h = (x - mean) * rstd * w + b   (float4 over the n dimension)
__global__ void gn_apply_k(const float* __restrict__ x,
                           const float* __restrict__ w,
                           const float* __restrict__ b) {
    const int idx4 = blockIdx.x * 256 + threadIdx.x;   // over float4s
    const int c  = (idx4 >> 8) & (CH - 1);             // NPIX/4 = 256 f4 per channel
    const int bb = idx4 >> 17;                         // CH*NPIX/4 = 2^17
    const int bg = bb * NGRP + (c >> 4);
    const float m = g_mean[bg], r = g_rstd[bg];
    const float sc = r * w[c];
    const float sh = b[c] - m * sc;
    float4 v = ((const float4*)x)[idx4];
    v.x = v.x * sc + sh; v.y = v.y * sc + sh;
    v.z = v.z * sc + sh; v.w = v.w * sc + sh;
    ((float4*)g_h)[idx4] = v;
}

// ---------------------------------------------------------------------------
// Generic batched fp32 GEMM, 128x128x8 tiles, 256 threads, 8x8 micro-tile,
// accumulation in packed f32x2.
//   C[m][n] (+= alpha * sum_k A(.)B(.))  [+ bias[m]] [+ res[m][n]]
//   A_KM: A stored [K][M] (ld=lda) else [M][K]
//   B_KN: B stored [K][N] (ld=ldb) else [N][K]
//   C row-major with ld = N. All dims are multiples of tile sizes.
// ---------------------------------------------------------------------------
template<bool A_KM, bool B_KN, bool BIAS, bool RES>
__global__ void __launch_bounds__(256, 2) gemm_k(
    const float* __restrict__ A, const float* __restrict__ B,
    float* __restrict__ C,
    const float* __restrict__ bias, const float* __restrict__ res,
    int M, int N, int K, int lda, int ldb,
    size_t sA, size_t sB, size_t sC, float alpha)
{
    const int bz = blockIdx.z;
    A += sA * bz; B += sB * bz; C += sC * bz;
    if (RES) res += sC * bz;

    __shared__ float As[8][128];
    __shared__ float Bs[8][128];

    const int tid = threadIdx.x;
    const int m0 = blockIdx.y * 128, n0 = blockIdx.x * 128;
    const int tr = tid >> 4, tc = tid & 15;   // 16x16 thread grid, 8x8 each

    unsigned long long acc[8][4];
    #pragma unroll
    for (int i = 0; i < 8; i++)
        #pragma unroll
        for (int j = 0; j < 4; j++) acc[i][j] = 0ull;   // (0.f, 0.f)

    for (int kt = 0; kt < K; kt += 8) {
        // ---- stage A tile ----
        if (A_KM) {
            const int r = tid >> 5, c4 = (tid & 31) << 2;      // 8 rows x 32 f4
            *(float4*)&As[r][c4] =
                *(const float4*)&A[(size_t)(kt + r) * lda + m0 + c4];
        } else {
            const int r = tid >> 1, c4 = (tid & 1) << 2;       // 128 rows x 2 f4
            float4 v = *(const float4*)&A[(size_t)(m0 + r) * lda + kt + c4];
            As[c4 + 0][r] = v.x; As[c4 + 1][r] = v.y;
            As[c4 + 2][r] = v.z; As[c4 + 3][r] = v.w;
        }
        // ---- stage B tile ----
        if (B_KN) {
            const int r = tid >> 5, c4 = (tid & 31) << 2;
            *(float4*)&Bs[r][c4] =
                *(const float4*)&B[(size_t)(kt + r) * ldb + n0 + c4];
        } else {
            const int r = tid >> 1, c4 = (tid & 1) << 2;
            float4 v = *(const float4*)&B[(size_t)(n0 + r) * ldb + kt + c4];
            Bs[c4 + 0][r] = v.x; Bs[c4 + 1][r] = v.y;
            Bs[c4 + 2][r] = v.z; Bs[c4 + 3][r] = v.w;
        }
        __syncthreads();

        #pragma unroll
        for (int k = 0; k < 8; k++) {
            float4 a0 = *(const float4*)&As[k][tr * 8];
            float4 a1 = *(const float4*)&As[k][tr * 8 + 4];
            float4 b0 = *(const float4*)&Bs[k][tc * 8];
            float4 b1 = *(const float4*)&Bs[k][tc * 8 + 4];
            unsigned long long bp[4] = { pk2(b0.x, b0.y), pk2(b0.z, b0.w),
                                         pk2(b1.x, b1.y), pk2(b1.z, b1.w) };
            float av[8] = { a0.x, a0.y, a0.z, a0.w, a1.x, a1.y, a1.z, a1.w };
            #pragma unroll
            for (int i = 0; i < 8; i++) {
                unsigned long long ad = pk2(av[i], av[i]);
                #pragma unroll
                for (int j = 0; j < 4; j++) fma2(acc[i][j], ad, bp[j]);
            }
        }
        __syncthreads();
    }

    // ---- epilogue ----
    #pragma unroll
    for (int i = 0; i < 8; i++) {
        const int row = m0 + tr * 8 + i;
        const float bv = BIAS ? bias[row] : 0.f;
        float* crow = C + (size_t)row * N + n0 + tc * 8;
        float vals[8];
        #pragma unroll
        for (int j = 0; j < 4; j++) {
            float2 t = up2(acc[i][j]);
            vals[2 * j + 0] = t.x * alpha + bv;
            vals[2 * j + 1] = t.y * alpha + bv;
        }
        if (RES) {
            const float* rrow = res + (size_t)row * N + n0 + tc * 8;
            float4 r0 = *(const float4*)&rrow[0];
            float4 r1 = *(const float4*)&rrow[4];
            vals[0] += r0.x; vals[1] += r0.y; vals[2] += r0.z; vals[3] += r0.w;
            vals[4] += r1.x; vals[5] += r1.y; vals[6] += r1.z; vals[7] += r1.w;
        }
        *(float4*)&crow[0] = make_float4(vals[0], vals[1], vals[2], vals[3]);
        *(float4*)&crow[4] = make_float4(vals[4], vals[5], vals[6], vals[7]);
    }
}

// ---------------------------------------------------------------------------
// Row softmax over 1024 elements. One block (256 threads) per row.
// ---------------------------------------------------------------------------
__global__ void softmax_k(float* __restrict__ S) {
    const size_t row = blockIdx.x;
    float4* p = (float4*)(S + row * (size_t)NPIX);
    float4 v = p[threadIdx.x];

    __shared__ float sh[8];
    __shared__ float bcast;

    float mx = fmaxf(fmaxf(v.x, v.y), fmaxf(v.z, v.w));
    mx = warp_max(mx);
    if (!(threadIdx.x & 31)) sh[threadIdx.x >> 5] = mx;
    __syncthreads();
    if (threadIdx.x < 32) {
        float t = (threadIdx.x < 8) ? sh[threadIdx.x] : -1e30f;
        t = warp_max(t);
        if (!threadIdx.x) bcast = t;
    }
    __syncthreads();
    mx = bcast;
    __syncthreads();

    v.x = __expf(v.x - mx); v.y = __expf(v.y - mx);
    v.z = __expf(v.z - mx); v.w = __expf(v.w - mx);
    float s = v.x + v.y + v.z + v.w;
    s = warp_sum(s);
    if (!(threadIdx.x & 31)) sh[threadIdx.x >> 5] = s;
    __syncthreads();
    if (threadIdx.x < 32) {
        float t = (threadIdx.x < 8) ? sh[threadIdx.x] : 0.f;
        t = warp_sum(t);
        if (!threadIdx.x) bcast = t;
    }
    __syncthreads();
    const float inv = 1.f / bcast;
    v.x *= inv; v.y *= inv; v.z *= inv; v.w *= inv;
    p[threadIdx.x] = v;
}

// ---------------------------------------------------------------------------
// Launch
// ---------------------------------------------------------------------------
extern "C" void kernel_launch(void* const* d_in, const int* in_sizes, int n_in,
                              void* d_out, int out_size) {
    const float* x  = (const float*)d_in[0];
    const float* nw = (const float*)d_in[1];
    const float* nb = (const float*)d_in[2];
    const float* qw = (const float*)d_in[3];
    const float* qb = (const float*)d_in[4];
    const float* pw = (const float*)d_in[5];
    const float* pb = (const float*)d_in[6];
    float* out = (float*)d_out;

    float *h, *qkv, *attn, *hout;
    cudaGetSymbolAddress((void**)&h,    g_h);
    cudaGetSymbolAddress((void**)&qkv,  g_qkv);
    cudaGetSymbolAddress((void**)&attn, g_attn);
    cudaGetSymbolAddress((void**)&hout, g_hout);

    const size_t sH   = (size_t)CH * NPIX;          // 512*1024
    const size_t sQKV = (size_t)3 * CH * NPIX;      // 1536*1024
    const size_t sAT  = (size_t)NPIX * NPIX;        // 1024*1024

    // 1) GroupNorm
    gn_stats_k<<<BATCH * NGRP, 256>>>(x);
    gn_apply_k<<<(BATCH * CH * NPIX) / (4 * 256), 256>>>(x, nw, nb);

    // 2) QKV = qkv_w @ h + qkv_b      (M=1536, N=1024, K=512)
    gemm_k<false, true, true, false><<<dim3(8, 12, BATCH), 256>>>(
        qw, h, qkv, qb, nullptr, 3 * CH, NPIX, CH, CH, NPIX,
        0, sH, sQKV, 1.f);

    // 3) scores[n][m] = scale * sum_c q[c][n] k[c][m]   (M=N=1024, K=512)
    const float scale = 0.044194173824159216f;   // 512^-0.5
    gemm_k<true, true, false, false><<<dim3(8, 8, BATCH), 256>>>(
        qkv, qkv + (size_t)CH * NPIX, attn, nullptr, nullptr,
        NPIX, NPIX, CH, NPIX, NPIX,
        sQKV, sQKV, sAT, scale);

    // 4) softmax rows
    softmax_k<<<BATCH * NPIX, 256>>>(attn);

    // 5) hout[c][n] = sum_m v[c][m] attn[n][m]   (M=512, N=1024, K=1024)
    gemm_k<false, false, false, false><<<dim3(8, 4, BATCH), 256>>>(
        qkv + (size_t)2 * CH * NPIX, attn, hout, nullptr, nullptr,
        CH, NPIX, NPIX, NPIX, NPIX,
        sQKV, sAT, sH, 1.f);

    // 6) out = x + proj_w @ hout + proj_b   (M=512, N=1024, K=512)
    gemm_k<false, true, true, true><<<dim3(8, 4, BATCH), 256>>>(
        pw, hout, out, pb, x,
        CH, NPIX, CH, CH, NPIX,
        0, sH, sH, 1.f);
}

// round 3
// speedup vs baseline: 1.0478x; 1.0478x over previous
#include <cuda_runtime.h>
#include <cuda_bf16.h>

// Problem constants
#define BATCH 32
#define CH    512
#define NPIX  1024   // H*W = 32*32
#define NGRP  32
#define CPG   16     // channels per group

// ---------------------------------------------------------------------------
// Scratch (device globals — no allocations allowed)
// ---------------------------------------------------------------------------
__device__ float g_mean[BATCH * NGRP];
__device__ float g_rstd[BATCH * NGRP];
__device__ float g_h   [(size_t)BATCH * CH * NPIX];        //  64 MiB
__device__ float g_qkv [(size_t)BATCH * 3 * CH * NPIX];    // 192 MiB
__device__ float g_attn[(size_t)BATCH * NPIX * NPIX];      // 128 MiB
__device__ float g_hout[(size_t)BATCH * CH * NPIX];        //  64 MiB

// ---------------------------------------------------------------------------
// Helpers
// ---------------------------------------------------------------------------
__device__ __forceinline__ float warp_sum(float v) {
    #pragma unroll
    for (int o = 16; o; o >>= 1) v += __shfl_xor_sync(0xffffffffu, v, o);
    return v;
}
__device__ __forceinline__ float warp_max(float v) {
    #pragma unroll
    for (int o = 16; o; o >>= 1) v = fmaxf(v, __shfl_xor_sync(0xffffffffu, v, o));
    return v;
}

// Split fp32 into bf16 hi + bf16 lo (x ~= hi + lo, residual ~2^-18 rel)
__device__ __forceinline__ void split2(float x, __nv_bfloat16& h, __nv_bfloat16& l) {
    h = __float2bfloat16_rn(x);
    l = __float2bfloat16_rn(x - __bfloat162float(h));
}

// m16n8k16 bf16 mma with fp32 accumulate
__device__ __forceinline__ void mma_bf16(float* d, const unsigned* a, const unsigned* b) {
    asm volatile(
        "mma.sync.aligned.m16n8k16.row.col.f32.bf16.bf16.f32 "
        "{%0,%1,%2,%3}, {%4,%5,%6,%7}, {%8,%9}, {%0,%1,%2,%3};"
        : "+f"(d[0]), "+f"(d[1]), "+f"(d[2]), "+f"(d[3])
        : "r"(a[0]), "r"(a[1]), "r"(a[2]), "r"(a[3]),
          "r"(b[0]), "r"(b[1]));
}

// ---------------------------------------------------------------------------
// GroupNorm stats: one block per (batch, group). Group slab is contiguous.
// ---------------------------------------------------------------------------
__global__ void gn_stats_k(const float* __restrict__ x) {
    const int bg = blockIdx.x;
    const float4* p = (const float4*)(x + (size_t)bg * (CPG * NPIX));
    float s = 0.f, ss = 0.f;
    for (int i = threadIdx.x; i < (CPG * NPIX) / 4; i += 256) {
        float4 v = p[i];
        s  += v.x + v.y + v.z + v.w;
        ss += v.x * v.x + v.y * v.y + v.z * v.z + v.w * v.w;
    }
    __shared__ float sh1[8], sh2[8];
    s = warp_sum(s); ss = warp_sum(ss);
    const int w = threadIdx.x >> 5, l = threadIdx.x & 31;
    if (!l) { sh1[w] = s; sh2[w] = ss; }
    __syncthreads();
    if (threadIdx.x < 32) {
        float a = (threadIdx.x < 8) ? sh1[threadIdx.x] : 0.f;
        float b = (threadIdx.x < 8) ? sh2[threadIdx.x] : 0.f;
        a = warp_sum(a); b = warp_sum(b);
        if (!threadIdx.x) {
            const float inv_n = 1.f / (float)(CPG * NPIX);
            float m   = a * inv_n;
            float var = b * inv_n - m * m;
            g_mean[bg] = m;
            g_rstd[bg] = rsqrtf(var + 1e-5f);
        }
    }
}

__global__ void gn_apply_k(const float* __restrict__ x,
                           const float* __restrict__ w,
                           const float* __restrict__ b) {
    const int idx4 = blockIdx.x * 256 + threadIdx.x;
    const int c  = (idx4 >> 8) & (CH - 1);
    const int bb = idx4 >> 17;
    const int bg = bb * NGRP + (c >> 4);
    const float m = g_mean[bg], r = g_rstd[bg];
    const float sc = r * w[c];
    const float sh = b[c] - m * sc;
    float4 v = ((const float4*)x)[idx4];
    v.x = v.x * sc + sh; v.y = v.y * sc + sh;
    v.z = v.z * sc + sh; v.w = v.w * sc + sh;
    ((float4*)g_h)[idx4] = v;
}

// ---------------------------------------------------------------------------
// Batched split-bf16 tensor-core GEMM.
//   C[m][n] = alpha * sum_k A(.)B(.)  [+ bias[m]] [+ res[m][n]]
//   A_KM: A stored [K][M] (ld=lda) else [M][K]
//   B_KN: B stored [K][N] (ld=ldb) else [N][K]
// Tiles: 128x128x32, 256 threads, 2x4 warp grid, warp tile 64x32,
// mma.sync m16n8k16 bf16, 3-term hi/lo split, fp32 accumulators.
// All dims multiples of tile sizes. Smem rows padded to 40 bf16 (bank-clean).
// ---------------------------------------------------------------------------
#define LDS_S 40

template<bool A_KM, bool B_KN, bool BIAS, bool RES>
__global__ void __launch_bounds__(256, 2) gemm_k(
    const float* __restrict__ A, const float* __restrict__ B,
    float* __restrict__ C,
    const float* __restrict__ bias, const float* __restrict__ res,
    int M, int N, int K, int lda, int ldb,
    size_t sA, size_t sB, size_t sC, float alpha)
{
    const int bz = blockIdx.z;
    A += sA * bz; B += sB * bz; C += sC * bz;
    if (RES) res += sC * bz;

    __shared__ __nv_bfloat16 As[2][128][LDS_S];   // [hi/lo][m][k]
    __shared__ __nv_bfloat16 Bs[2][128][LDS_S];   // [hi/lo][n][k]

    const int tid = threadIdx.x;
    const int m0 = blockIdx.y * 128, n0 = blockIdx.x * 128;
    const int wid = tid >> 5, lane = tid & 31;
    const int wm = (wid >> 2) * 64;     // warp row 0/64
    const int wn = (wid & 3) * 32;      // warp col 0/32/64/96
    const int gid = lane >> 2, tid4 = lane & 3;

    float acc[4][4][4];
    #pragma unroll
    for (int mi = 0; mi < 4; mi++)
        #pragma unroll
        for (int ni = 0; ni < 4; ni++)
            #pragma unroll
            for (int j = 0; j < 4; j++) acc[mi][ni][j] = 0.f;

    for (int kt = 0; kt < K; kt += 32) {
        // ---- stage A tile (fp32 -> bf16 hi/lo) ----
        if (A_KM) {
            #pragma unroll
            for (int i = tid; i < 1024; i += 256) {
                const int k = i >> 5, m = (i & 31) << 2;
                float4 v = *(const float4*)&A[(size_t)(kt + k) * lda + m0 + m];
                __nv_bfloat16 h, l;
                split2(v.x, h, l); As[0][m+0][k] = h; As[1][m+0][k] = l;
                split2(v.y, h, l); As[0][m+1][k] = h; As[1][m+1][k] = l;
                split2(v.z, h, l); As[0][m+2][k] = h; As[1][m+2][k] = l;
                split2(v.w, h, l); As[0][m+3][k] = h; As[1][m+3][k] = l;
            }
        } else {
            #pragma unroll
            for (int i = tid; i < 1024; i += 256) {
                const int row = i >> 3, c4 = (i & 7) << 2;
                float4 v = *(const float4*)&A[(size_t)(m0 + row) * lda + kt + c4];
                __nv_bfloat16 h0,h1,h2,h3,l0,l1,l2,l3;
                split2(v.x, h0, l0); split2(v.y, h1, l1);
                split2(v.z, h2, l2); split2(v.w, h3, l3);
                *(__nv_bfloat162*)&As[0][row][c4 + 0] = __nv_bfloat162(h0, h1);
                *(__nv_bfloat162*)&As[0][row][c4 + 2] = __nv_bfloat162(h2, h3);
                *(__nv_bfloat162*)&As[1][row][c4 + 0] = __nv_bfloat162(l0, l1);
                *(__nv_bfloat162*)&As[1][row][c4 + 2] = __nv_bfloat162(l2, l3);
            }
        }
        // ---- stage B tile ----
        if (B_KN) {
            #pragma unroll
            for (int i = tid; i < 1024; i += 256) {
                const int k = i >> 5, n = (i & 31) << 2;
                float4 v = *(const float4*)&B[(size_t)(kt + k) * ldb + n0 + n];
                __nv_bfloat16 h, l;
                split2(v.x, h, l); Bs[0][n+0][k] = h; Bs[1][n+0][k] = l;
                split2(v.y, h, l); Bs[0][n+1][k] = h; Bs[1][n+1][k] = l;
                split2(v.z, h, l); Bs[0][n+2][k] = h; Bs[1][n+2][k] = l;
                split2(v.w, h, l); Bs[0][n+3][k] = h; Bs[1][n+3][k] = l;
            }
        } else {
            #pragma unroll
            for (int i = tid; i < 1024; i += 256) {
                const int row = i >> 3, c4 = (i & 7) << 2;
                float4 v = *(const float4*)&B[(size_t)(n0 + row) * ldb + kt + c4];
                __nv_bfloat16 h0,h1,h2,h3,l0,l1,l2,l3;
                split2(v.x, h0, l0); split2(v.y, h1, l1);
                split2(v.z, h2, l2); split2(v.w, h3, l3);
                *(__nv_bfloat162*)&Bs[0][row][c4 + 0] = __nv_bfloat162(h0, h1);
                *(__nv_bfloat162*)&Bs[0][row][c4 + 2] = __nv_bfloat162(h2, h3);
                *(__nv_bfloat162*)&Bs[1][row][c4 + 0] = __nv_bfloat162(l0, l1);
                *(__nv_bfloat162*)&Bs[1][row][c4 + 2] = __nv_bfloat162(l2, l3);
            }
        }
        __syncthreads();

        // ---- compute: 2 k-steps of 16 ----
        #pragma unroll
        for (int ks = 0; ks < 32; ks += 16) {
            // B fragments (hi & lo), 4 n-frags
            unsigned bh[4][2], bl[4][2];
            #pragma unroll
            for (int ni = 0; ni < 4; ni++) {
                const int nr = wn + ni * 8 + gid;
                bh[ni][0] = *(const unsigned*)&Bs[0][nr][ks + tid4 * 2];
                bh[ni][1] = *(const unsigned*)&Bs[0][nr][ks + 8 + tid4 * 2];
                bl[ni][0] = *(const unsigned*)&Bs[1][nr][ks + tid4 * 2];
                bl[ni][1] = *(const unsigned*)&Bs[1][nr][ks + 8 + tid4 * 2];
            }
            #pragma unroll
            for (int mi = 0; mi < 4; mi++) {
                const int r0 = wm + mi * 16 + gid;
                unsigned ah[4], al[4];
                ah[0] = *(const unsigned*)&As[0][r0    ][ks + tid4 * 2];
                ah[1] = *(const unsigned*)&As[0][r0 + 8][ks + tid4 * 2];
                ah[2] = *(const unsigned*)&As[0][r0    ][ks + 8 + tid4 * 2];
                ah[3] = *(const unsigned*)&As[0][r0 + 8][ks + 8 + tid4 * 2];
                al[0] = *(const unsigned*)&As[1][r0    ][ks + tid4 * 2];
                al[1] = *(const unsigned*)&As[1][r0 + 8][ks + tid4 * 2];
                al[2] = *(const unsigned*)&As[1][r0    ][ks + 8 + tid4 * 2];
                al[3] = *(const unsigned*)&As[1][r0 + 8][ks + 8 + tid4 * 2];
                #pragma unroll
                for (int ni = 0; ni < 4; ni++) {
                    mma_bf16(acc[mi][ni], ah, bh[ni]);   // hi*hi
                    mma_bf16(acc[mi][ni], ah, bl[ni]);   // hi*lo
                    mma_bf16(acc[mi][ni], al, bh[ni]);   // lo*hi
                }
            }
        }
        __syncthreads();
    }

    // ---- epilogue: direct gmem writes (float2 per fragment half) ----
    #pragma unroll
    for (int mi = 0; mi < 4; mi++) {
        #pragma unroll
        for (int half = 0; half < 2; half++) {
            const int row = m0 + wm + mi * 16 + gid + half * 8;
            const float bv = BIAS ? bias[row] : 0.f;
            #pragma unroll
            for (int ni = 0; ni < 4; ni++) {
                const int col = n0 + wn + ni * 8 + tid4 * 2;
                float v0 = acc[mi][ni][half * 2 + 0] * alpha + bv;
                float v1 = acc[mi][ni][half * 2 + 1] * alpha + bv;
                if (RES) {
                    const float* rp = res + (size_t)row * N + col;
                    v0 += rp[0]; v1 += rp[1];
                }
                *(float2*)&C[(size_t)row * N + col] = make_float2(v0, v1);
            }
        }
    }
}

// ---------------------------------------------------------------------------
// Row softmax over 1024 elements. One block (256 threads) per row.
// ---------------------------------------------------------------------------
__global__ void softmax_k(float* __restrict__ S) {
    const size_t row = blockIdx.x;
    float4* p = (float4*)(S + row * (size_t)NPIX);
    float4 v = p[threadIdx.x];

    __shared__ float sh[8];
    __shared__ float bcast;

    float mx = fmaxf(fmaxf(v.x, v.y), fmaxf(v.z, v.w));
    mx = warp_max(mx);
    if (!(threadIdx.x & 31)) sh[threadIdx.x >> 5] = mx;
    __syncthreads();
    if (threadIdx.x < 32) {
        float t = (threadIdx.x < 8) ? sh[threadIdx.x] : -1e30f;
        t = warp_max(t);
        if (!threadIdx.x) bcast = t;
    }
    __syncthreads();
    mx = bcast;
    __syncthreads();

    v.x = __expf(v.x - mx); v.y = __expf(v.y - mx);
    v.z = __expf(v.z - mx); v.w = __expf(v.w - mx);
    float s = v.x + v.y + v.z + v.w;
    s = warp_sum(s);
    if (!(threadIdx.x & 31)) sh[threadIdx.x >> 5] = s;
    __syncthreads();
    if (threadIdx.x < 32) {
        float t = (threadIdx.x < 8) ? sh[threadIdx.x] : 0.f;
        t = warp_sum(t);
        if (!threadIdx.x) bcast = t;
    }
    __syncthreads();
    const float inv = 1.f / bcast;
    v.x *= inv; v.y *= inv; v.z *= inv; v.w *= inv;
    p[threadIdx.x] = v;
}

// ---------------------------------------------------------------------------
// Launch
// ---------------------------------------------------------------------------
extern "C" void kernel_launch(void* const* d_in, const int* in_sizes, int n_in,
                              void* d_out, int out_size) {
    const float* x  = (const float*)d_in[0];
    const float* nw = (const float*)d_in[1];
    const float* nb = (const float*)d_in[2];
    const float* qw = (const float*)d_in[3];
    const float* qb = (const float*)d_in[4];
    const float* pw = (const float*)d_in[5];
    const float* pb = (const float*)d_in[6];
    float* out = (float*)d_out;

    float *h, *qkv, *attn, *hout;
    cudaGetSymbolAddress((void**)&h,    g_h);
    cudaGetSymbolAddress((void**)&qkv,  g_qkv);
    cudaGetSymbolAddress((void**)&attn, g_attn);
    cudaGetSymbolAddress((void**)&hout, g_hout);

    const size_t sH   = (size_t)CH * NPIX;
    const size_t sQKV = (size_t)3 * CH * NPIX;
    const size_t sAT  = (size_t)NPIX * NPIX;

    // 1) GroupNorm
    gn_stats_k<<<BATCH * NGRP, 256>>>(x);
    gn_apply_k<<<(BATCH * CH * NPIX) / (4 * 256), 256>>>(x, nw, nb);

    // 2) QKV = qkv_w @ h + qkv_b      (M=1536, N=1024, K=512)
    gemm_k<false, true, true, false><<<dim3(8, 12, BATCH), 256>>>(
        qw, h, qkv, qb, nullptr, 3 * CH, NPIX, CH, CH, NPIX,
        0, sH, sQKV, 1.f);

    // 3) scores[n][m] = scale * sum_c q[c][n] k[c][m]   (M=N=1024, K=512)
    const float scale = 0.044194173824159216f;   // 512^-0.5
    gemm_k<true, true, false, false><<<dim3(8, 8, BATCH), 256>>>(
        qkv, qkv + (size_t)CH * NPIX, attn, nullptr, nullptr,
        NPIX, NPIX, CH, NPIX, NPIX,
        sQKV, sQKV, sAT, scale);

    // 4) softmax rows
    softmax_k<<<BATCH * NPIX, 256>>>(attn);

    // 5) hout[c][n] = sum_m v[c][m] attn[n][m]   (M=512, N=1024, K=1024)
    gemm_k<false, false, false, false><<<dim3(8, 4, BATCH), 256>>>(
        qkv + (size_t)2 * CH * NPIX, attn, hout, nullptr, nullptr,
        CH, NPIX, NPIX, NPIX, NPIX,
        sQKV, sAT, sH, 1.f);

    // 6) out = x + proj_w @ hout + proj_b   (M=512, N=1024, K=512)
    gemm_k<false, true, true, true><<<dim3(8, 4, BATCH), 256>>>(
        pw, hout, out, pb, x,
        CH, NPIX, CH, CH, NPIX,
        0, sH, sH, 1.f);
}

// round 4
// speedup vs baseline: 2.6410x; 2.5206x over previous
#include <cuda_runtime.h>
#include <cuda_bf16.h>

// Problem constants
#define BATCH 32
#define CH    512
#define NPIX  1024   // H*W = 32*32
#define NGRP  32
#define CPG   16     // channels per group

// ---------------------------------------------------------------------------
// Scratch (device globals — no allocations allowed)
// ---------------------------------------------------------------------------
__device__ float g_mean[BATCH * NGRP];
__device__ float g_rstd[BATCH * NGRP];

// bf16 hi/lo planes for every GEMM operand
__device__ __nv_bfloat16 g_wq  [2][(size_t)3 * CH * CH];                 // qkv_w
__device__ __nv_bfloat16 g_wp  [2][(size_t)CH * CH];                     // proj_w
__device__ __nv_bfloat16 g_hb  [2][(size_t)BATCH * CH * NPIX];           // groupnorm out
__device__ __nv_bfloat16 g_qkvb[2][(size_t)BATCH * 3 * CH * NPIX];       // qkv out
__device__ __nv_bfloat16 g_attb[2][(size_t)BATCH * NPIX * NPIX];         // softmax out
__device__ __nv_bfloat16 g_houtb[2][(size_t)BATCH * CH * NPIX];          // attn*V out
__device__ float g_attn[(size_t)BATCH * NPIX * NPIX];                    // scores (fp32 for softmax)

// ---------------------------------------------------------------------------
// Helpers
// ---------------------------------------------------------------------------
__device__ __forceinline__ float warp_sum(float v) {
    #pragma unroll
    for (int o = 16; o; o >>= 1) v += __shfl_xor_sync(0xffffffffu, v, o);
    return v;
}
__device__ __forceinline__ float warp_max(float v) {
    #pragma unroll
    for (int o = 16; o; o >>= 1) v = fmaxf(v, __shfl_xor_sync(0xffffffffu, v, o));
    return v;
}
__device__ __forceinline__ void split2(float x, __nv_bfloat16& h, __nv_bfloat16& l) {
    h = __float2bfloat16_rn(x);
    l = __float2bfloat16_rn(x - __bfloat162float(h));
}

__device__ __forceinline__ void mma_bf16(float* d, const unsigned* a, const unsigned* b) {
    asm volatile(
        "mma.sync.aligned.m16n8k16.row.col.f32.bf16.bf16.f32 "
        "{%0,%1,%2,%3}, {%4,%5,%6,%7}, {%8,%9}, {%0,%1,%2,%3};"
        : "+f"(d[0]), "+f"(d[1]), "+f"(d[2]), "+f"(d[3])
        : "r"(a[0]), "r"(a[1]), "r"(a[2]), "r"(a[3]),
          "r"(b[0]), "r"(b[1]));
}

template<bool T>
__device__ __forceinline__ void ldsm4(unsigned r[4], unsigned addr) {
    if (T)
        asm volatile("ldmatrix.sync.aligned.m8n8.x4.trans.shared.b16 {%0,%1,%2,%3}, [%4];"
                     : "=r"(r[0]), "=r"(r[1]), "=r"(r[2]), "=r"(r[3]) : "r"(addr));
    else
        asm volatile("ldmatrix.sync.aligned.m8n8.x4.shared.b16 {%0,%1,%2,%3}, [%4];"
                     : "=r"(r[0]), "=r"(r[1]), "=r"(r[2]), "=r"(r[3]) : "r"(addr));
}
template<bool T>
__device__ __forceinline__ void ldsm2(unsigned r[2], unsigned addr) {
    if (T)
        asm volatile("ldmatrix.sync.aligned.m8n8.x2.trans.shared.b16 {%0,%1}, [%2];"
                     : "=r"(r[0]), "=r"(r[1]) : "r"(addr));
    else
        asm volatile("ldmatrix.sync.aligned.m8n8.x2.shared.b16 {%0,%1}, [%2];"
                     : "=r"(r[0]), "=r"(r[1]) : "r"(addr));
}

__device__ __forceinline__ void cp16(unsigned dst, const void* src) {
    asm volatile("cp.async.ca.shared.global [%0], [%1], 16;" :: "r"(dst), "l"(src));
}
__device__ __forceinline__ void cp_commit() { asm volatile("cp.async.commit_group;"); }

// ---------------------------------------------------------------------------
// Weight / activation split kernels (fp32 -> bf16 hi + lo planes)
// ---------------------------------------------------------------------------
__global__ void wsplit_k(const float* __restrict__ src,
                         __nv_bfloat16* __restrict__ hi,
                         __nv_bfloat16* __restrict__ lo) {
    const int i4 = blockIdx.x * 256 + threadIdx.x;
    float4 v = ((const float4*)src)[i4];
    __nv_bfloat16 h0,h1,h2,h3,l0,l1,l2,l3;
    split2(v.x,h0,l0); split2(v.y,h1,l1); split2(v.z,h2,l2); split2(v.w,h3,l3);
    ((__nv_bfloat162*)hi)[i4*2+0] = __nv_bfloat162(h0,h1);
    ((__nv_bfloat162*)hi)[i4*2+1] = __nv_bfloat162(h2,h3);
    ((__nv_bfloat162*)lo)[i4*2+0] = __nv_bfloat162(l0,l1);
    ((__nv_bfloat162*)lo)[i4*2+1] = __nv_bfloat162(l2,l3);
}

// ---------------------------------------------------------------------------
// GroupNorm
// ---------------------------------------------------------------------------
__global__ void gn_stats_k(const float* __restrict__ x) {
    const int bg = blockIdx.x;
    const float4* p = (const float4*)(x + (size_t)bg * (CPG * NPIX));
    float s = 0.f, ss = 0.f;
    for (int i = threadIdx.x; i < (CPG * NPIX) / 4; i += 256) {
        float4 v = p[i];
        s  += v.x + v.y + v.z + v.w;
        ss += v.x * v.x + v.y * v.y + v.z * v.z + v.w * v.w;
    }
    __shared__ float sh1[8], sh2[8];
    s = warp_sum(s); ss = warp_sum(ss);
    const int w = threadIdx.x >> 5, l = threadIdx.x & 31;
    if (!l) { sh1[w] = s; sh2[w] = ss; }
    __syncthreads();
    if (threadIdx.x < 32) {
        float a = (threadIdx.x < 8) ? sh1[threadIdx.x] : 0.f;
        float b = (threadIdx.x < 8) ? sh2[threadIdx.x] : 0.f;
        a = warp_sum(a); b = warp_sum(b);
        if (!threadIdx.x) {
            const float inv_n = 1.f / (float)(CPG * NPIX);
            float m   = a * inv_n;
            float var = b * inv_n - m * m;
            g_mean[bg] = m;
            g_rstd[bg] = rsqrtf(var + 1e-5f);
        }
    }
}

__global__ void gn_apply_k(const float* __restrict__ x,
                           const float* __restrict__ w,
                           const float* __restrict__ b) {
    const int idx4 = blockIdx.x * 256 + threadIdx.x;
    const int c  = (idx4 >> 8) & (CH - 1);
    const int bb = idx4 >> 17;
    const int bg = bb * NGRP + (c >> 4);
    const float m = g_mean[bg], r = g_rstd[bg];
    const float sc = r * w[c];
    const float sh = b[c] - m * sc;
    float4 v = ((const float4*)x)[idx4];
    v.x = v.x * sc + sh; v.y = v.y * sc + sh;
    v.z = v.z * sc + sh; v.w = v.w * sc + sh;
    __nv_bfloat16 h0,h1,h2,h3,l0,l1,l2,l3;
    split2(v.x,h0,l0); split2(v.y,h1,l1); split2(v.z,h2,l2); split2(v.w,h3,l3);
    ((__nv_bfloat162*)g_hb[0])[idx4*2+0] = __nv_bfloat162(h0,h1);
    ((__nv_bfloat162*)g_hb[0])[idx4*2+1] = __nv_bfloat162(h2,h3);
    ((__nv_bfloat162*)g_hb[1])[idx4*2+0] = __nv_bfloat162(l0,l1);
    ((__nv_bfloat162*)g_hb[1])[idx4*2+1] = __nv_bfloat162(l2,l3);
}

// ---------------------------------------------------------------------------
// Batched split-bf16 tensor-core GEMM, cp.async double-buffered, ldmatrix.
//   logical C[m][n] = alpha * sum_k A(m,k)*B(k,n)  [+bias[m]] [+res]
//   A_T: A source stored [K][M] (ld=lda), smem [k][m], ldmatrix.trans
//        else source [M][K], smem [m][k], ldmatrix
//   B_T: B source stored [K][N] (ld=ldb), smem [k][n], ldmatrix.trans
//        else source [N][K], smem [n][k], ldmatrix
//   SPLIT_OUT: write bf16 hi/lo planes; else fp32 C (+alpha, bias, res)
// Tiles: 128x128x32, 256 threads, warp tile 64x32, m16n8k16, 3-term split.
// All dims multiples of tile sizes.
// ---------------------------------------------------------------------------
template<bool A_T, bool B_T, bool BIAS, bool RES, bool SPLIT_OUT>
__global__ void __launch_bounds__(256, 2) gemm_bf(
    const __nv_bfloat16* __restrict__ Ahi, const __nv_bfloat16* __restrict__ Alo,
    const __nv_bfloat16* __restrict__ Bhi, const __nv_bfloat16* __restrict__ Blo,
    float* __restrict__ C,
    __nv_bfloat16* __restrict__ Chi, __nv_bfloat16* __restrict__ Clo,
    const float* __restrict__ bias, const float* __restrict__ res,
    int M, int N, int K, int lda, int ldb,
    size_t sA, size_t sB, size_t sC, float alpha)
{
    // per-plane smem tile bytes (row-pitch padded: 40 bf16 / 136 bf16)
    constexpr int A_PB   = (A_T ? 32 * 136 : 128 * 40) * 2;
    constexpr int B_PB   = (B_T ? 32 * 136 : 128 * 40) * 2;
    constexpr int STAGE  = 2 * A_PB + 2 * B_PB;

    extern __shared__ char smem[];
    const unsigned sbase = (unsigned)__cvta_generic_to_shared(smem);

    const int bz = blockIdx.z;
    Ahi += sA * bz; Alo += sA * bz;
    Bhi += sB * bz; Blo += sB * bz;
    if (!SPLIT_OUT) { C += sC * bz; if (RES) res += sC * bz; }
    else            { Chi += sC * bz; Clo += sC * bz; }

    const int tid = threadIdx.x;
    const int m0 = blockIdx.y * 128, n0 = blockIdx.x * 128;
    const int wid = tid >> 5, lane = tid & 31;
    const int wm = (wid >> 2) * 64;
    const int wn = (wid & 3) * 32;
    const int gid = lane >> 2, tid4 = lane & 3;

    float acc[4][4][4];
    #pragma unroll
    for (int mi = 0; mi < 4; mi++)
        #pragma unroll
        for (int ni = 0; ni < 4; ni++)
            #pragma unroll
            for (int j = 0; j < 4; j++) acc[mi][ni][j] = 0.f;

    // ---- async stage loader ----
    auto load_stage = [&](int st, int kt) {
        const unsigned base = sbase + st * STAGE;
        // A tiles (hi plane then lo plane), 512 16B-chunks per plane
        #pragma unroll
        for (int c = tid; c < 1024; c += 256) {
            const int plane = c >> 9, idx = c & 511;
            const __nv_bfloat16* sp = plane ? Alo : Ahi;
            if (A_T) {
                const int row = idx >> 4, seg = idx & 15;
                cp16(base + plane * A_PB + row * 272 + seg * 16,
                     sp + (size_t)(kt + row) * lda + m0 + seg * 8);
            } else {
                const int row = idx >> 2, seg = idx & 3;
                cp16(base + plane * A_PB + row * 80 + seg * 16,
                     sp + (size_t)(m0 + row) * lda + kt + seg * 8);
            }
        }
        // B tiles
        #pragma unroll
        for (int c = tid; c < 1024; c += 256) {
            const int plane = c >> 9, idx = c & 511;
            const __nv_bfloat16* sp = plane ? Blo : Bhi;
            if (B_T) {
                const int row = idx >> 4, seg = idx & 15;
                cp16(base + 2 * A_PB + plane * B_PB + row * 272 + seg * 16,
                     sp + (size_t)(kt + row) * ldb + n0 + seg * 8);
            } else {
                const int row = idx >> 2, seg = idx & 3;
                cp16(base + 2 * A_PB + plane * B_PB + row * 80 + seg * 16,
                     sp + (size_t)(n0 + row) * ldb + kt + seg * 8);
            }
        }
    };

    // ldmatrix lane-address components (byte offsets within tile, minus ks/frag)
    // A non-trans:  (m0f + (lane&15)) * 80 + (ks + 8*(lane>>4)) * 2
    // A trans:      (ks + (lane&7) + 8*(lane>>4)) * 272 + (m0f + 8*((lane>>3)&1)) * 2
    // B non-trans:  (n0f + (lane&7)) * 80 + (ks + 8*((lane>>3)&1)) * 2
    // B trans:      (ks + (lane&7) + 8*((lane>>3)&1)) * 272 + n0f * 2
    const int la15 = lane & 15, la7 = lane & 7;
    const int la_hi4 = lane >> 4, la_b3 = (lane >> 3) & 1;

    const int T = K / 32;
    load_stage(0, 0);
    cp_commit();

    for (int t = 0; t < T; t++) {
        if (t + 1 < T) { load_stage((t + 1) & 1, (t + 1) * 32); cp_commit(); }
        if (t + 1 < T) { asm volatile("cp.async.wait_group 1;"); }
        else           { asm volatile("cp.async.wait_group 0;"); }
        __syncthreads();

        const unsigned aBase = sbase + (t & 1) * STAGE;
        const unsigned bBase = aBase + 2 * A_PB;

        #pragma unroll
        for (int ks = 0; ks < 32; ks += 16) {
            unsigned bh[4][2], bl[4][2];
            #pragma unroll
            for (int ni = 0; ni < 4; ni++) {
                const int nf = wn + ni * 8;
                unsigned ah_off, al_off;
                if (B_T) {
                    ah_off = bBase + (ks + la7 + 8 * la_b3) * 272 + nf * 2;
                } else {
                    ah_off = bBase + (nf + la7) * 80 + (ks + 8 * la_b3) * 2;
                }
                al_off = ah_off + B_PB;
                ldsm2<B_T>(bh[ni], ah_off);
                ldsm2<B_T>(bl[ni], al_off);
            }
            #pragma unroll
            for (int mi = 0; mi < 4; mi++) {
                const int mf = wm + mi * 16;
                unsigned ah[4], al[4];
                unsigned off;
                if (A_T) {
                    off = aBase + (ks + la7 + 8 * la_hi4) * 272 + (mf + 8 * la_b3) * 2;
                } else {
                    off = aBase + (mf + la15) * 80 + (ks + 8 * la_hi4) * 2;
                }
                ldsm4<A_T>(ah, off);
                ldsm4<A_T>(al, off + A_PB);
                #pragma unroll
                for (int ni = 0; ni < 4; ni++) {
                    mma_bf16(acc[mi][ni], ah, bh[ni]);   // hi*hi
                    mma_bf16(acc[mi][ni], ah, bl[ni]);   // hi*lo
                    mma_bf16(acc[mi][ni], al, bh[ni]);   // lo*hi
                }
            }
        }
        __syncthreads();
    }

    // ---- epilogue ----
    #pragma unroll
    for (int mi = 0; mi < 4; mi++) {
        #pragma unroll
        for (int half = 0; half < 2; half++) {
            const int row = m0 + wm + mi * 16 + gid + half * 8;
            const float bv = BIAS ? bias[row] : 0.f;
            #pragma unroll
            for (int ni = 0; ni < 4; ni++) {
                const int col = n0 + wn + ni * 8 + tid4 * 2;
                float v0 = acc[mi][ni][half * 2 + 0] * alpha + bv;
                float v1 = acc[mi][ni][half * 2 + 1] * alpha + bv;
                if (SPLIT_OUT) {
                    __nv_bfloat16 h0, l0, h1, l1;
                    split2(v0, h0, l0); split2(v1, h1, l1);
                    *(__nv_bfloat162*)&Chi[(size_t)row * N + col] = __nv_bfloat162(h0, h1);
                    *(__nv_bfloat162*)&Clo[(size_t)row * N + col] = __nv_bfloat162(l0, l1);
                } else {
                    if (RES) {
                        const float* rp = res + (size_t)row * N + col;
                        v0 += rp[0]; v1 += rp[1];
                    }
                    *(float2*)&C[(size_t)row * N + col] = make_float2(v0, v1);
                }
            }
        }
    }
}

// ---------------------------------------------------------------------------
// Row softmax over 1024 elements + bf16 hi/lo split output.
// ---------------------------------------------------------------------------
__global__ void softmax_k(const float* __restrict__ S) {
    const size_t row = blockIdx.x;
    const float4* p = (const float4*)(S + row * (size_t)NPIX);
    float4 v = p[threadIdx.x];

    __shared__ float sh[8];
    __shared__ float bcast;

    float mx = fmaxf(fmaxf(v.x, v.y), fmaxf(v.z, v.w));
    mx = warp_max(mx);
    if (!(threadIdx.x & 31)) sh[threadIdx.x >> 5] = mx;
    __syncthreads();
    if (threadIdx.x < 32) {
        float t = (threadIdx.x < 8) ? sh[threadIdx.x] : -1e30f;
        t = warp_max(t);
        if (!threadIdx.x) bcast = t;
    }
    __syncthreads();
    mx = bcast;
    __syncthreads();

    v.x = __expf(v.x - mx); v.y = __expf(v.y - mx);
    v.z = __expf(v.z - mx); v.w = __expf(v.w - mx);
    float s = v.x + v.y + v.z + v.w;
    s = warp_sum(s);
    if (!(threadIdx.x & 31)) sh[threadIdx.x >> 5] = s;
    __syncthreads();
    if (threadIdx.x < 32) {
        float t = (threadIdx.x < 8) ? sh[threadIdx.x] : 0.f;
        t = warp_sum(t);
        if (!threadIdx.x) bcast = t;
    }
    __syncthreads();
    const float inv = 1.f / bcast;
    v.x *= inv; v.y *= inv; v.z *= inv; v.w *= inv;

    __nv_bfloat16 h0,h1,h2,h3,l0,l1,l2,l3;
    split2(v.x,h0,l0); split2(v.y,h1,l1); split2(v.z,h2,l2); split2(v.w,h3,l3);
    const size_t i2 = row * (NPIX / 2) + threadIdx.x * 2;
    ((__nv_bfloat162*)g_attb[0])[i2 + 0] = __nv_bfloat162(h0,h1);
    ((__nv_bfloat162*)g_attb[0])[i2 + 1] = __nv_bfloat162(h2,h3);
    ((__nv_bfloat162*)g_attb[1])[i2 + 0] = __nv_bfloat162(l0,l1);
    ((__nv_bfloat162*)g_attb[1])[i2 + 1] = __nv_bfloat162(l2,l3);
}

// ---------------------------------------------------------------------------
// Launch
// ---------------------------------------------------------------------------
extern "C" void kernel_launch(void* const* d_in, const int* in_sizes, int n_in,
                              void* d_out, int out_size) {
    const float* x  = (const float*)d_in[0];
    const float* nw = (const float*)d_in[1];
    const float* nb = (const float*)d_in[2];
    const float* qw = (const float*)d_in[3];
    const float* qb = (const float*)d_in[4];
    const float* pw = (const float*)d_in[5];
    const float* pb = (const float*)d_in[6];
    float* out = (float*)d_out;

    __nv_bfloat16 *wq0, *wq1, *wp0, *wp1, *hb0, *hb1, *qk0, *qk1, *at0, *at1, *ho0, *ho1;
    float* attn;
    cudaGetSymbolAddress((void**)&wq0, g_wq);   wq1 = wq0 + (size_t)3*CH*CH;
    cudaGetSymbolAddress((void**)&wp0, g_wp);   wp1 = wp0 + (size_t)CH*CH;
    cudaGetSymbolAddress((void**)&hb0, g_hb);   hb1 = hb0 + (size_t)BATCH*CH*NPIX;
    cudaGetSymbolAddress((void**)&qk0, g_qkvb); qk1 = qk0 + (size_t)BATCH*3*CH*NPIX;
    cudaGetSymbolAddress((void**)&at0, g_attb); at1 = at0 + (size_t)BATCH*NPIX*NPIX;
    cudaGetSymbolAddress((void**)&ho0, g_houtb); ho1 = ho0 + (size_t)BATCH*CH*NPIX;
    cudaGetSymbolAddress((void**)&attn, g_attn);

    const size_t sH   = (size_t)CH * NPIX;
    const size_t sQKV = (size_t)3 * CH * NPIX;
    const size_t sAT  = (size_t)NPIX * NPIX;

    // dynamic smem sizes per config
    const int SM_AT_BT = 2 * (4 * 32*136*2);                       // 69632
    const int SM_A_BT  = 2 * (2 * 128*40*2 + 2 * 32*136*2);        // 75776
    const int SM_A_B   = 2 * (4 * 128*40*2);                       // 81920

    cudaFuncSetAttribute(gemm_bf<false,true ,true ,false,true >, cudaFuncAttributeMaxDynamicSharedMemorySize, 81920);
    cudaFuncSetAttribute(gemm_bf<true ,true ,false,false,false>, cudaFuncAttributeMaxDynamicSharedMemorySize, 81920);
    cudaFuncSetAttribute(gemm_bf<false,false,false,false,true >, cudaFuncAttributeMaxDynamicSharedMemorySize, 81920);
    cudaFuncSetAttribute(gemm_bf<false,true ,true ,true ,false>, cudaFuncAttributeMaxDynamicSharedMemorySize, 81920);

    // 0) split weights to bf16 hi/lo
    wsplit_k<<<(3*CH*CH)/(4*256), 256>>>(qw, wq0, wq1);
    wsplit_k<<<(CH*CH)/(4*256), 256>>>(pw, wp0, wp1);

    // 1) GroupNorm (writes split h)
    gn_stats_k<<<BATCH * NGRP, 256>>>(x);
    gn_apply_k<<<(BATCH * CH * NPIX) / (4 * 256), 256>>>(x, nw, nb);

    // 2) QKV = qkv_w @ h + qkv_b  (M=1536,N=1024,K=512)  A:[M][K]  B:[K][N]
    gemm_bf<false,true,true,false,true><<<dim3(8,12,BATCH), 256, SM_A_BT>>>(
        wq0, wq1, hb0, hb1, nullptr, qk0, qk1, qb, nullptr,
        3*CH, NPIX, CH, CH, NPIX, 0, sH, sQKV, 1.f);

    // 3) scores[n][m] = scale * sum_c q[c][n] k[c][m]  (M=N=1024,K=512) A:[K][M] B:[K][N]
    const float scale = 0.044194173824159216f;
    gemm_bf<true,true,false,false,false><<<dim3(8,8,BATCH), 256, SM_AT_BT>>>(
        qk0, qk1, qk0 + sH, qk1 + sH, attn, nullptr, nullptr, nullptr, nullptr,
        NPIX, NPIX, CH, NPIX, NPIX, sQKV, sQKV, sAT, scale);

    // 4) softmax rows (+ split output)
    softmax_k<<<BATCH * NPIX, 256>>>(attn);

    // 5) hout[c][n] = sum_m v[c][m] attn[n][m]  (M=512,N=1024,K=1024)  A:[M][K] B:[N][K]
    gemm_bf<false,false,false,false,true><<<dim3(8,4,BATCH), 256, SM_A_B>>>(
        qk0 + 2*sH, qk1 + 2*sH, at0, at1, nullptr, ho0, ho1, nullptr, nullptr,
        CH, NPIX, NPIX, NPIX, NPIX, sQKV, sAT, sH, 1.f);

    // 6) out = x + proj_w @ hout + proj_b  (M=512,N=1024,K=512)  A:[M][K] B:[K][N]
    gemm_bf<false,true,true,true,false><<<dim3(8,4,BATCH), 256, SM_A_BT>>>(
        wp0, wp1, ho0, ho1, out, nullptr, nullptr, pb, x,
        CH, NPIX, CH, CH, NPIX, 0, sH, sH, 1.f);
}

// round 9
// speedup vs baseline: 2.6909x; 1.0189x over previous
#include <cuda_runtime.h>
#include <cuda_bf16.h>

// Problem constants
#define BATCH 32
#define CH    512
#define NPIX  1024   // H*W = 32*32
#define NGRP  32
#define CPG   16     // channels per group

// ---------------------------------------------------------------------------
// Scratch (device globals — no allocations allowed)
// ---------------------------------------------------------------------------
__device__ float g_mean[BATCH * NGRP];
__device__ float g_rstd[BATCH * NGRP];

// bf16 hi/lo planes for every GEMM operand
__device__ __nv_bfloat16 g_wq  [2][(size_t)3 * CH * CH];                 // qkv_w
__device__ __nv_bfloat16 g_wp  [2][(size_t)CH * CH];                     // proj_w
__device__ __nv_bfloat16 g_hb  [2][(size_t)BATCH * CH * NPIX];           // groupnorm out
__device__ __nv_bfloat16 g_qkvb[2][(size_t)BATCH * 3 * CH * NPIX];       // qkv out
__device__ __nv_bfloat16 g_attb[2][(size_t)BATCH * NPIX * NPIX];         // softmax out
__device__ __nv_bfloat16 g_houtb[2][(size_t)BATCH * CH * NPIX];          // attn*V out
__device__ float g_attn[(size_t)BATCH * NPIX * NPIX];                    // scores (fp32)

// ---------------------------------------------------------------------------
// Helpers
// ---------------------------------------------------------------------------
__device__ __forceinline__ float warp_sum(float v) {
    #pragma unroll
    for (int o = 16; o; o >>= 1) v += __shfl_xor_sync(0xffffffffu, v, o);
    return v;
}
__device__ __forceinline__ float warp_max(float v) {
    #pragma unroll
    for (int o = 16; o; o >>= 1) v = fmaxf(v, __shfl_xor_sync(0xffffffffu, v, o));
    return v;
}
__device__ __forceinline__ void split2(float x, __nv_bfloat16& h, __nv_bfloat16& l) {
    h = __float2bfloat16_rn(x);
    l = __float2bfloat16_rn(x - __bfloat162float(h));
}

__device__ __forceinline__ void mma_bf16(float* d, const unsigned* a, const unsigned* b) {
    asm volatile(
        "mma.sync.aligned.m16n8k16.row.col.f32.bf16.bf16.f32 "
        "{%0,%1,%2,%3}, {%4,%5,%6,%7}, {%8,%9}, {%0,%1,%2,%3};"
        : "+f"(d[0]), "+f"(d[1]), "+f"(d[2]), "+f"(d[3])
        : "r"(a[0]), "r"(a[1]), "r"(a[2]), "r"(a[3]),
          "r"(b[0]), "r"(b[1]));
}

template<bool T>
__device__ __forceinline__ void ldsm4(unsigned r[4], unsigned addr) {
    if (T)
        asm volatile("ldmatrix.sync.aligned.m8n8.x4.trans.shared.b16 {%0,%1,%2,%3}, [%4];"
                     : "=r"(r[0]), "=r"(r[1]), "=r"(r[2]), "=r"(r[3]) : "r"(addr));
    else
        asm volatile("ldmatrix.sync.aligned.m8n8.x4.shared.b16 {%0,%1,%2,%3}, [%4];"
                     : "=r"(r[0]), "=r"(r[1]), "=r"(r[2]), "=r"(r[3]) : "r"(addr));
}

__device__ __forceinline__ void cp16(unsigned dst, const void* src) {
    asm volatile("cp.async.cg.shared.global [%0], [%1], 16;" :: "r"(dst), "l"(src));
}
__device__ __forceinline__ void cp_commit() { asm volatile("cp.async.commit_group;"); }

// ---------------------------------------------------------------------------
// Weight / activation split kernels (fp32 -> bf16 hi + lo planes)
// ---------------------------------------------------------------------------
__global__ void wsplit_k(const float* __restrict__ src,
                         __nv_bfloat16* __restrict__ hi,
                         __nv_bfloat16* __restrict__ lo) {
    const int i4 = blockIdx.x * 256 + threadIdx.x;
    float4 v = ((const float4*)src)[i4];
    __nv_bfloat16 h0,h1,h2,h3,l0,l1,l2,l3;
    split2(v.x,h0,l0); split2(v.y,h1,l1); split2(v.z,h2,l2); split2(v.w,h3,l3);
    ((__nv_bfloat162*)hi)[i4*2+0] = __nv_bfloat162(h0,h1);
    ((__nv_bfloat162*)hi)[i4*2+1] = __nv_bfloat162(h2,h3);
    ((__nv_bfloat162*)lo)[i4*2+0] = __nv_bfloat162(l0,l1);
    ((__nv_bfloat162*)lo)[i4*2+1] = __nv_bfloat162(l2,l3);
}

// ---------------------------------------------------------------------------
// GroupNorm
// ---------------------------------------------------------------------------
__global__ void gn_stats_k(const float* __restrict__ x) {
    const int bg = blockIdx.x;
    const float4* p = (const float4*)(x + (size_t)bg * (CPG * NPIX));
    float s = 0.f, ss = 0.f;
    for (int i = threadIdx.x; i < (CPG * NPIX) / 4; i += 256) {
        float4 v = p[i];
        s  += v.x + v.y + v.z + v.w;
        ss += v.x * v.x + v.y * v.y + v.z * v.z + v.w * v.w;
    }
    __shared__ float sh1[8], sh2[8];
    s = warp_sum(s); ss = warp_sum(ss);
    const int w = threadIdx.x >> 5, l = threadIdx.x & 31;
    if (!l) { sh1[w] = s; sh2[w] = ss; }
    __syncthreads();
    if (threadIdx.x < 32) {
        float a = (threadIdx.x < 8) ? sh1[threadIdx.x] : 0.f;
        float b = (threadIdx.x < 8) ? sh2[threadIdx.x] : 0.f;
        a = warp_sum(a); b = warp_sum(b);
        if (!threadIdx.x) {
            const float inv_n = 1.f / (float)(CPG * NPIX);
            float m   = a * inv_n;
            float var = b * inv_n - m * m;
            g_mean[bg] = m;
            g_rstd[bg] = rsqrtf(var + 1e-5f);
        }
    }
}

__global__ void gn_apply_k(const float* __restrict__ x,
                           const float* __restrict__ w,
                           const float* __restrict__ b) {
    const int idx4 = blockIdx.x * 256 + threadIdx.x;
    const int c  = (idx4 >> 8) & (CH - 1);
    const int bb = idx4 >> 17;
    const int bg = bb * NGRP + (c >> 4);
    const float m = g_mean[bg], r = g_rstd[bg];
    const float sc = r * w[c];
    const float sh = b[c] - m * sc;
    float4 v = ((const float4*)x)[idx4];
    v.x = v.x * sc + sh; v.y = v.y * sc + sh;
    v.z = v.z * sc + sh; v.w = v.w * sc + sh;
    __nv_bfloat16 h0,h1,h2,h3,l0,l1,l2,l3;
    split2(v.x,h0,l0); split2(v.y,h1,l1); split2(v.z,h2,l2); split2(v.w,h3,l3);
    ((__nv_bfloat162*)g_hb[0])[idx4*2+0] = __nv_bfloat162(h0,h1);
    ((__nv_bfloat162*)g_hb[0])[idx4*2+1] = __nv_bfloat162(h2,h3);
    ((__nv_bfloat162*)g_hb[1])[idx4*2+0] = __nv_bfloat162(l0,l1);
    ((__nv_bfloat162*)g_hb[1])[idx4*2+1] = __nv_bfloat162(l2,l3);
}

// ---------------------------------------------------------------------------
// Batched split-bf16 tensor-core GEMM, cp.async double-buffered, ldmatrix x4.
//   logical C[m][n] = alpha * sum_k A(m,k)*B(k,n)  [+bias[m]] [+res]
//   A_T: A source stored [K][M] (ld=lda), smem [k][m], ldmatrix.trans
//   B_T: B source stored [K][N] (ld=ldb), smem [k][n], ldmatrix.trans
//   SPLIT_OUT: write bf16 hi/lo planes; else fp32 C (+alpha, bias, res)
// CTA tile 128x128x32, 128 threads (2x2 warps), warp tile 64x64,
// m16n8k16 bf16, 3-term hi/lo split. All dims multiples of tile sizes.
// ---------------------------------------------------------------------------
template<bool A_T, bool B_T, bool BIAS, bool RES, bool SPLIT_OUT>
__global__ void __launch_bounds__(128, 2) gemm_bf(
    const __nv_bfloat16* __restrict__ Ahi, const __nv_bfloat16* __restrict__ Alo,
    const __nv_bfloat16* __restrict__ Bhi, const __nv_bfloat16* __restrict__ Blo,
    float* __restrict__ C,
    __nv_bfloat16* __restrict__ Chi, __nv_bfloat16* __restrict__ Clo,
    const float* __restrict__ bias, const float* __restrict__ res,
    int M, int N, int K, int lda, int ldb,
    size_t sA, size_t sB, size_t sC, float alpha)
{
    // per-plane smem tile bytes (row-pitch padded: 40 bf16 / 136 bf16)
    constexpr int A_PB   = (A_T ? 32 * 136 : 128 * 40) * 2;
    constexpr int B_PB   = (B_T ? 32 * 136 : 128 * 40) * 2;
    constexpr int STAGE  = 2 * A_PB + 2 * B_PB;

    extern __shared__ char smem[];
    const unsigned sbase = (unsigned)__cvta_generic_to_shared(smem);

    const int bz = blockIdx.z;
    Ahi += sA * bz; Alo += sA * bz;
    Bhi += sB * bz; Blo += sB * bz;
    if (!SPLIT_OUT) { C += sC * bz; if (RES) res += sC * bz; }
    else            { Chi += sC * bz; Clo += sC * bz; }

    const int tid = threadIdx.x;
    const int m0 = blockIdx.y * 128, n0 = blockIdx.x * 128;
    const int wid = tid >> 5, lane = tid & 31;
    const int wm = (wid >> 1) * 64;     // warp rows: 0 / 64
    const int wn = (wid & 1) * 64;      // warp cols: 0 / 64
    const int gid = lane >> 2, tid4 = lane & 3;

    float acc[4][8][4];
    #pragma unroll
    for (int mi = 0; mi < 4; mi++)
        #pragma unroll
        for (int ni = 0; ni < 8; ni++)
            #pragma unroll
            for (int j = 0; j < 4; j++) acc[mi][ni][j] = 0.f;

    // ---- async stage loader (layout identical to validated round-4 code) ----
    auto load_stage = [&](int st, int kt) {
        const unsigned base = sbase + st * STAGE;
        #pragma unroll
        for (int c = tid; c < 1024; c += 128) {
            const int plane = c >> 9, idx = c & 511;
            const __nv_bfloat16* sp = plane ? Alo : Ahi;
            if (A_T) {
                const int row = idx >> 4, seg = idx & 15;
                cp16(base + plane * A_PB + row * 272 + seg * 16,
                     sp + (size_t)(kt + row) * lda + m0 + seg * 8);
            } else {
                const int row = idx >> 2, seg = idx & 3;
                cp16(base + plane * A_PB + row * 80 + seg * 16,
                     sp + (size_t)(m0 + row) * lda + kt + seg * 8);
            }
        }
        #pragma unroll
        for (int c = tid; c < 1024; c += 128) {
            const int plane = c >> 9, idx = c & 511;
            const __nv_bfloat16* sp = plane ? Blo : Bhi;
            if (B_T) {
                const int row = idx >> 4, seg = idx & 15;
                cp16(base + 2 * A_PB + plane * B_PB + row * 272 + seg * 16,
                     sp + (size_t)(kt + row) * ldb + n0 + seg * 8);
            } else {
                const int row = idx >> 2, seg = idx & 3;
                cp16(base + 2 * A_PB + plane * B_PB + row * 80 + seg * 16,
                     sp + (size_t)(n0 + row) * ldb + kt + seg * 8);
            }
        }
    };

    const int la15 = lane & 15, la7 = lane & 7;
    const int la_hi4 = lane >> 4, la_b3 = (lane >> 3) & 1;

    const int T = K / 32;
    load_stage(0, 0);
    cp_commit();

    for (int t = 0; t < T; t++) {
        if (t + 1 < T) { load_stage((t + 1) & 1, (t + 1) * 32); cp_commit(); }
        if (t + 1 < T) { asm volatile("cp.async.wait_group 1;"); }
        else           { asm volatile("cp.async.wait_group 0;"); }
        __syncthreads();

        const unsigned aBase = sbase + (t & 1) * STAGE;
        const unsigned bBase = aBase + 2 * A_PB;

        #pragma unroll
        for (int ks = 0; ks < 32; ks += 16) {
            // B fragments: 8 n-frags of 8 cols, loaded pairwise via ldsm4
            unsigned bh[8][2], bl[8][2];
            #pragma unroll
            for (int nip = 0; nip < 4; nip++) {
                const int nf = wn + nip * 16;
                unsigned off;
                if (B_T) {
                    // rows: k = ks + la7 + 8*la_b3 ; cols: nf + 8*la_hi4
                    off = bBase + (ks + la7 + 8 * la_b3) * 272 + (nf + 8 * la_hi4) * 2;
                } else {
                    // rows: n = nf + la7 + 8*la_hi4 ; cols: ks + 8*la_b3
                    off = bBase + (nf + la7 + 8 * la_hi4) * 80 + (ks + 8 * la_b3) * 2;
                }
                unsigned r[4];
                ldsm4<B_T>(r, off);
                bh[nip*2][0] = r[0]; bh[nip*2][1] = r[1];
                bh[nip*2+1][0] = r[2]; bh[nip*2+1][1] = r[3];
                ldsm4<B_T>(r, off + B_PB);
                bl[nip*2][0] = r[0]; bl[nip*2][1] = r[1];
                bl[nip*2+1][0] = r[2]; bl[nip*2+1][1] = r[3];
            }
            #pragma unroll
            for (int mi = 0; mi < 4; mi++) {
                const int mf = wm + mi * 16;
                unsigned ah[4], al[4];
                unsigned off;
                if (A_T) {
                    off = aBase + (ks + la7 + 8 * la_hi4) * 272 + (mf + 8 * la_b3) * 2;
                } else {
                    off = aBase + (mf + la15) * 80 + (ks + 8 * la_hi4) * 2;
                }
                ldsm4<A_T>(ah, off);
                ldsm4<A_T>(al, off + A_PB);
                #pragma unroll
                for (int ni = 0; ni < 8; ni++) {
                    mma_bf16(acc[mi][ni], ah, bh[ni]);   // hi*hi
                    mma_bf16(acc[mi][ni], ah, bl[ni]);   // hi*lo
                    mma_bf16(acc[mi][ni], al, bh[ni]);   // lo*hi
                }
            }
        }
        __syncthreads();
    }

    // ---- epilogue ----
    #pragma unroll
    for (int mi = 0; mi < 4; mi++) {
        #pragma unroll
        for (int half = 0; half < 2; half++) {
            const int row = m0 + wm + mi * 16 + gid + half * 8;
            const float bv = BIAS ? bias[row] : 0.f;
            #pragma unroll
            for (int ni = 0; ni < 8; ni++) {
                const int col = n0 + wn + ni * 8 + tid4 * 2;
                float v0 = acc[mi][ni][half * 2 + 0] * alpha + bv;
                float v1 = acc[mi][ni][half * 2 + 1] * alpha + bv;
                if (SPLIT_OUT) {
                    __nv_bfloat16 h0, l0, h1, l1;
                    split2(v0, h0, l0); split2(v1, h1, l1);
                    *(__nv_bfloat162*)&Chi[(size_t)row * N + col] = __nv_bfloat162(h0, h1);
                    *(__nv_bfloat162*)&Clo[(size_t)row * N + col] = __nv_bfloat162(l0, l1);
                } else {
                    if (RES) {
                        const float* rp = res + (size_t)row * N + col;
                        v0 += rp[0]; v1 += rp[1];
                    }
                    *(float2*)&C[(size_t)row * N + col] = make_float2(v0, v1);
                }
            }
        }
    }
}

// ---------------------------------------------------------------------------
// Row softmax over 1024 elements + bf16 hi/lo split output.
// ---------------------------------------------------------------------------
__global__ void softmax_k(const float* __restrict__ S) {
    const size_t row = blockIdx.x;
    const float4* p = (const float4*)(S + row * (size_t)NPIX);
    float4 v = p[threadIdx.x];

    __shared__ float sh[8];
    __shared__ float bcast;

    float mx = fmaxf(fmaxf(v.x, v.y), fmaxf(v.z, v.w));
    mx = warp_max(mx);
    if (!(threadIdx.x & 31)) sh[threadIdx.x >> 5] = mx;
    __syncthreads();
    if (threadIdx.x < 32) {
        float t = (threadIdx.x < 8) ? sh[threadIdx.x] : -1e30f;
        t = warp_max(t);
        if (!threadIdx.x) bcast = t;
    }
    __syncthreads();
    mx = bcast;
    __syncthreads();

    v.x = __expf(v.x - mx); v.y = __expf(v.y - mx);
    v.z = __expf(v.z - mx); v.w = __expf(v.w - mx);
    float s = v.x + v.y + v.z + v.w;
    s = warp_sum(s);
    if (!(threadIdx.x & 31)) sh[threadIdx.x >> 5] = s;
    __syncthreads();
    if (threadIdx.x < 32) {
        float t = (threadIdx.x < 8) ? sh[threadIdx.x] : 0.f;
        t = warp_sum(t);
        if (!threadIdx.x) bcast = t;
    }
    __syncthreads();
    const float inv = 1.f / bcast;
    v.x *= inv; v.y *= inv; v.z *= inv; v.w *= inv;

    __nv_bfloat16 h0,h1,h2,h3,l0,l1,l2,l3;
    split2(v.x,h0,l0); split2(v.y,h1,l1); split2(v.z,h2,l2); split2(v.w,h3,l3);
    const size_t i2 = row * (NPIX / 2) + threadIdx.x * 2;
    ((__nv_bfloat162*)g_attb[0])[i2 + 0] = __nv_bfloat162(h0,h1);
    ((__nv_bfloat162*)g_attb[0])[i2 + 1] = __nv_bfloat162(h2,h3);
    ((__nv_bfloat162*)g_attb[1])[i2 + 0] = __nv_bfloat162(l0,l1);
    ((__nv_bfloat162*)g_attb[1])[i2 + 1] = __nv_bfloat162(l2,l3);
}

// ---------------------------------------------------------------------------
// Launch
// ---------------------------------------------------------------------------
extern "C" void kernel_launch(void* const* d_in, const int* in_sizes, int n_in,
                              void* d_out, int out_size) {
    const float* x  = (const float*)d_in[0];
    const float* nw = (const float*)d_in[1];
    const float* nb = (const float*)d_in[2];
    const float* qw = (const float*)d_in[3];
    const float* qb = (const float*)d_in[4];
    const float* pw = (const float*)d_in[5];
    const float* pb = (const float*)d_in[6];
    float* out = (float*)d_out;

    __nv_bfloat16 *wq0, *wq1, *wp0, *wp1, *hb0, *hb1, *qk0, *qk1, *at0, *at1, *ho0, *ho1;
    float* attn;
    cudaGetSymbolAddress((void**)&wq0, g_wq);   wq1 = wq0 + (size_t)3*CH*CH;
    cudaGetSymbolAddress((void**)&wp0, g_wp);   wp1 = wp0 + (size_t)CH*CH;
    cudaGetSymbolAddress((void**)&hb0, g_hb);   hb1 = hb0 + (size_t)BATCH*CH*NPIX;
    cudaGetSymbolAddress((void**)&qk0, g_qkvb); qk1 = qk0 + (size_t)BATCH*3*CH*NPIX;
    cudaGetSymbolAddress((void**)&at0, g_attb); at1 = at0 + (size_t)BATCH*NPIX*NPIX;
    cudaGetSymbolAddress((void**)&ho0, g_houtb); ho1 = ho0 + (size_t)BATCH*CH*NPIX;
    cudaGetSymbolAddress((void**)&attn, g_attn);

    const size_t sH   = (size_t)CH * NPIX;
    const size_t sQKV = (size_t)3 * CH * NPIX;
    const size_t sAT  = (size_t)NPIX * NPIX;

    // dynamic smem sizes per config
    const int SM_AT_BT = 2 * (4 * 32*136*2);                       // 69632
    const int SM_A_BT  = 2 * (2 * 128*40*2 + 2 * 32*136*2);        // 75776
    const int SM_A_B   = 2 * (4 * 128*40*2);                       // 81920

    cudaFuncSetAttribute(gemm_bf<false,true ,true ,false,true >, cudaFuncAttributeMaxDynamicSharedMemorySize, 81920);
    cudaFuncSetAttribute(gemm_bf<true ,true ,false,false,false>, cudaFuncAttributeMaxDynamicSharedMemorySize, 81920);
    cudaFuncSetAttribute(gemm_bf<false,false,false,false,true >, cudaFuncAttributeMaxDynamicSharedMemorySize, 81920);
    cudaFuncSetAttribute(gemm_bf<false,true ,true ,true ,false>, cudaFuncAttributeMaxDynamicSharedMemorySize, 81920);

    // 0) split weights to bf16 hi/lo
    wsplit_k<<<(3*CH*CH)/(4*256), 256>>>(qw, wq0, wq1);
    wsplit_k<<<(CH*CH)/(4*256), 256>>>(pw, wp0, wp1);

    // 1) GroupNorm (writes split h)
    gn_stats_k<<<BATCH * NGRP, 256>>>(x);
    gn_apply_k<<<(BATCH * CH * NPIX) / (4 * 256), 256>>>(x, nw, nb);

    // 2) QKV = qkv_w @ h + qkv_b  (M=1536,N=1024,K=512)  A:[M][K]  B:[K][N]
    gemm_bf<false,true,true,false,true><<<dim3(8,12,BATCH), 128, SM_A_BT>>>(
        wq0, wq1, hb0, hb1, nullptr, qk0, qk1, qb, nullptr,
        3*CH, NPIX, CH, CH, NPIX, 0, sH, sQKV, 1.f);

    // 3) scores[n][m] = scale * sum_c q[c][n] k[c][m]  (M=N=1024,K=512) A:[K][M] B:[K][N]
    const float scale = 0.044194173824159216f;
    gemm_bf<true,true,false,false,false><<<dim3(8,8,BATCH), 128, SM_AT_BT>>>(
        qk0, qk1, qk0 + sH, qk1 + sH, attn, nullptr, nullptr, nullptr, nullptr,
        NPIX, NPIX, CH, NPIX, NPIX, sQKV, sQKV, sAT, scale);

    // 4) softmax rows (+ split output)
    softmax_k<<<BATCH * NPIX, 256>>>(attn);

    // 5) hout[c][n] = sum_m v[c][m] attn[n][m]  (M=512,N=1024,K=1024)  A:[M][K] B:[N][K]
    gemm_bf<false,false,false,false,true><<<dim3(8,4,BATCH), 128, SM_A_B>>>(
        qk0 + 2*sH, qk1 + 2*sH, at0, at1, nullptr, ho0, ho1, nullptr, nullptr,
        CH, NPIX, NPIX, NPIX, NPIX, sQKV, sAT, sH, 1.f);

    // 6) out = x + proj_w @ hout + proj_b  (M=512,N=1024,K=512)  A:[M][K] B:[K][N]
    gemm_bf<false,true,true,true,false><<<dim3(8,4,BATCH), 128, SM_A_BT>>>(
        wp0, wp1, ho0, ho1, out, nullptr, nullptr, pb, x,
        CH, NPIX, CH, CH, NPIX, 0, sH, sH, 1.f);
}

// round 11
// speedup vs baseline: 3.7848x; 1.4065x over previous
#include <cuda_runtime.h>
#include <cuda_fp16.h>

// Problem constants
#define BATCH 32
#define CH    512
#define NPIX  1024   // H*W = 32*32
#define NGRP  32
#define CPG   16     // channels per group

// ---------------------------------------------------------------------------
// Scratch (device globals — no allocations allowed)
// ---------------------------------------------------------------------------
__device__ float g_mean[BATCH * NGRP];
__device__ float g_rstd[BATCH * NGRP];

// fp16 planes. Tensors consumed as "A" keep hi+lo; consumed only as "B" keep hi.
__device__ __half g_wq  [2][(size_t)3 * CH * CH];                 // qkv_w (A)
__device__ __half g_wp  [2][(size_t)CH * CH];                     // proj_w (A)
__device__ __half g_hb     [(size_t)BATCH * CH * NPIX];           // groupnorm out (B only)
__device__ __half g_qkvb[2][(size_t)BATCH * 3 * CH * NPIX];       // qkv out (q,v as A; k as B)
__device__ __half g_attb   [(size_t)BATCH * NPIX * NPIX];         // softmax out (B only)
__device__ __half g_houtb  [(size_t)BATCH * CH * NPIX];           // attn*V out (B only)
__device__ float g_attn[(size_t)BATCH * NPIX * NPIX];             // scores (fp32)

// ---------------------------------------------------------------------------
// Helpers
// ---------------------------------------------------------------------------
__device__ __forceinline__ float warp_sum(float v) {
    #pragma unroll
    for (int o = 16; o; o >>= 1) v += __shfl_xor_sync(0xffffffffu, v, o);
    return v;
}
__device__ __forceinline__ float warp_max(float v) {
    #pragma unroll
    for (int o = 16; o; o >>= 1) v = fmaxf(v, __shfl_xor_sync(0xffffffffu, v, o));
    return v;
}
__device__ __forceinline__ void split2h(float x, __half& h, __half& l) {
    h = __float2half_rn(x);
    l = __float2half_rn(x - __half2float(h));
}

__device__ __forceinline__ void mma_f16(float* d, const unsigned* a, const unsigned* b) {
    asm volatile(
        "mma.sync.aligned.m16n8k16.row.col.f32.f16.f16.f32 "
        "{%0,%1,%2,%3}, {%4,%5,%6,%7}, {%8,%9}, {%0,%1,%2,%3};"
        : "+f"(d[0]), "+f"(d[1]), "+f"(d[2]), "+f"(d[3])
        : "r"(a[0]), "r"(a[1]), "r"(a[2]), "r"(a[3]),
          "r"(b[0]), "r"(b[1]));
}

template<bool T>
__device__ __forceinline__ void ldsm4(unsigned r[4], unsigned addr) {
    if (T)
        asm volatile("ldmatrix.sync.aligned.m8n8.x4.trans.shared.b16 {%0,%1,%2,%3}, [%4];"
                     : "=r"(r[0]), "=r"(r[1]), "=r"(r[2]), "=r"(r[3]) : "r"(addr));
    else
        asm volatile("ldmatrix.sync.aligned.m8n8.x4.shared.b16 {%0,%1,%2,%3}, [%4];"
                     : "=r"(r[0]), "=r"(r[1]), "=r"(r[2]), "=r"(r[3]) : "r"(addr));
}

__device__ __forceinline__ void cp16(unsigned dst, const void* src) {
    asm volatile("cp.async.cg.shared.global [%0], [%1], 16;" :: "r"(dst), "l"(src));
}
__device__ __forceinline__ void cp_commit() { asm volatile("cp.async.commit_group;"); }

// ---------------------------------------------------------------------------
// Weight split kernels (fp32 -> fp16 hi + lo planes)
// ---------------------------------------------------------------------------
__global__ void wsplit_k(const float* __restrict__ src,
                         __half* __restrict__ hi,
                         __half* __restrict__ lo) {
    const int i4 = blockIdx.x * 256 + threadIdx.x;
    float4 v = ((const float4*)src)[i4];
    __half h0,h1,h2,h3,l0,l1,l2,l3;
    split2h(v.x,h0,l0); split2h(v.y,h1,l1); split2h(v.z,h2,l2); split2h(v.w,h3,l3);
    ((__half2*)hi)[i4*2+0] = __halves2half2(h0,h1);
    ((__half2*)hi)[i4*2+1] = __halves2half2(h2,h3);
    ((__half2*)lo)[i4*2+0] = __halves2half2(l0,l1);
    ((__half2*)lo)[i4*2+1] = __halves2half2(l2,l3);
}

// ---------------------------------------------------------------------------
// GroupNorm
// ---------------------------------------------------------------------------
__global__ void gn_stats_k(const float* __restrict__ x) {
    const int bg = blockIdx.x;
    const float4* p = (const float4*)(x + (size_t)bg * (CPG * NPIX));
    float s = 0.f, ss = 0.f;
    for (int i = threadIdx.x; i < (CPG * NPIX) / 4; i += 256) {
        float4 v = p[i];
        s  += v.x + v.y + v.z + v.w;
        ss += v.x * v.x + v.y * v.y + v.z * v.z + v.w * v.w;
    }
    __shared__ float sh1[8], sh2[8];
    s = warp_sum(s); ss = warp_sum(ss);
    const int w = threadIdx.x >> 5, l = threadIdx.x & 31;
    if (!l) { sh1[w] = s; sh2[w] = ss; }
    __syncthreads();
    if (threadIdx.x < 32) {
        float a = (threadIdx.x < 8) ? sh1[threadIdx.x] : 0.f;
        float b = (threadIdx.x < 8) ? sh2[threadIdx.x] : 0.f;
        a = warp_sum(a); b = warp_sum(b);
        if (!threadIdx.x) {
            const float inv_n = 1.f / (float)(CPG * NPIX);
            float m   = a * inv_n;
            float var = b * inv_n - m * m;
            g_mean[bg] = m;
            g_rstd[bg] = rsqrtf(var + 1e-5f);
        }
    }
}

// h consumed only as B operand -> single fp16 plane
__global__ void gn_apply_k(const float* __restrict__ x,
                           const float* __restrict__ w,
                           const float* __restrict__ b) {
    const int idx4 = blockIdx.x * 256 + threadIdx.x;
    const int c  = (idx4 >> 8) & (CH - 1);
    const int bb = idx4 >> 17;
    const int bg = bb * NGRP + (c >> 4);
    const float m = g_mean[bg], r = g_rstd[bg];
    const float sc = r * w[c];
    const float sh = b[c] - m * sc;
    float4 v = ((const float4*)x)[idx4];
    ((__half2*)g_hb)[idx4*2+0] = __floats2half2_rn(v.x*sc+sh, v.y*sc+sh);
    ((__half2*)g_hb)[idx4*2+1] = __floats2half2_rn(v.z*sc+sh, v.w*sc+sh);
}

// ---------------------------------------------------------------------------
// Batched split-fp16 tensor-core GEMM, 3-stage cp.async pipeline, ldmatrix x4.
//   logical C[m][n] = alpha * sum_k A(m,k)*B(k,n)
//   A = Ahi + Alo (fp16 2-term split); B = single fp16 plane.
//   A_T: A source stored [K][M] (ld=lda), smem [k][m], ldmatrix.trans
//   B_T: B source stored [K][N] (ld=ldb), smem [k][n], ldmatrix.trans
//   OUTM: 0 = fp32*alpha | 1 = fp32 + bias[row] + res | 2 = fp16 hi/lo planes
//         + bias[row]    | 3 = single fp16 plane (rounded)
// CTA tile 128x128x32, 128 threads (2x2 warps), warp tile 64x64, m16n8k16.
// All dims multiples of tile sizes.
// ---------------------------------------------------------------------------
template<bool A_T, bool B_T, int OUTM>
__global__ void __launch_bounds__(128, 2) gemm_h(
    const __half* __restrict__ Ahi, const __half* __restrict__ Alo,
    const __half* __restrict__ Bhi,
    float* __restrict__ C,
    __half* __restrict__ Chi, __half* __restrict__ Clo,
    const float* __restrict__ bias, const float* __restrict__ res,
    int M, int N, int K, int lda, int ldb,
    size_t sA, size_t sB, size_t sC, float alpha)
{
    // per-plane smem tile bytes (row-pitch padded: 40 h / 136 h)
    constexpr int A_PB  = (A_T ? 32 * 136 : 128 * 40) * 2;
    constexpr int B_PB  = (B_T ? 32 * 136 : 128 * 40) * 2;
    constexpr int STAGE = 2 * A_PB + B_PB;

    extern __shared__ char smem[];
    const unsigned sbase = (unsigned)__cvta_generic_to_shared(smem);

    const int bz = blockIdx.z;
    Ahi += sA * bz; Alo += sA * bz; Bhi += sB * bz;
    if (OUTM == 0 || OUTM == 1) { C += sC * bz; if (OUTM == 1) res += sC * bz; }
    else { Chi += sC * bz; if (OUTM == 2) Clo += sC * bz; }

    const int tid = threadIdx.x;
    const int m0 = blockIdx.y * 128, n0 = blockIdx.x * 128;
    const int wid = tid >> 5, lane = tid & 31;
    const int wm = (wid >> 1) * 64;     // warp rows: 0 / 64
    const int wn = (wid & 1) * 64;      // warp cols: 0 / 64
    const int gid = lane >> 2, tid4 = lane & 3;

    float acc[4][8][4];
    #pragma unroll
    for (int mi = 0; mi < 4; mi++)
        #pragma unroll
        for (int ni = 0; ni < 8; ni++)
            #pragma unroll
            for (int j = 0; j < 4; j++) acc[mi][ni][j] = 0.f;

    // ---- async stage loader ----
    auto load_stage = [&](int st, int kt) {
        const unsigned base = sbase + st * STAGE;
        // A: 2 planes x 512 16B-chunks
        #pragma unroll
        for (int c = tid; c < 1024; c += 128) {
            const int plane = c >> 9, idx = c & 511;
            const __half* sp = plane ? Alo : Ahi;
            if (A_T) {
                const int row = idx >> 4, seg = idx & 15;
                cp16(base + plane * A_PB + row * 272 + seg * 16,
                     sp + (size_t)(kt + row) * lda + m0 + seg * 8);
            } else {
                const int row = idx >> 2, seg = idx & 3;
                cp16(base + plane * A_PB + row * 80 + seg * 16,
                     sp + (size_t)(m0 + row) * lda + kt + seg * 8);
            }
        }
        // B: 1 plane x 512 chunks
        #pragma unroll
        for (int c = tid; c < 512; c += 128) {
            if (B_T) {
                const int row = c >> 4, seg = c & 15;
                cp16(base + 2 * A_PB + row * 272 + seg * 16,
                     Bhi + (size_t)(kt + row) * ldb + n0 + seg * 8);
            } else {
                const int row = c >> 2, seg = c & 3;
                cp16(base + 2 * A_PB + row * 80 + seg * 16,
                     Bhi + (size_t)(n0 + row) * ldb + kt + seg * 8);
            }
        }
    };

    const int la15 = lane & 15, la7 = lane & 7;
    const int la_hi4 = lane >> 4, la_b3 = (lane >> 3) & 1;

    const int T = K / 32;   // always >= 16
    load_stage(0, 0);  cp_commit();
    load_stage(1, 32); cp_commit();

    for (int t = 0; t < T; t++) {
        asm volatile("cp.async.wait_group 1;");   // stage t complete
        __syncthreads();                          // also fences reuse of slot (t+2)%3
        if (t + 2 < T) load_stage((t + 2) % 3, (t + 2) * 32);
        cp_commit();                              // uniform group accounting

        const unsigned aBase = sbase + (t % 3) * STAGE;
        const unsigned bBase = aBase + 2 * A_PB;

        #pragma unroll
        for (int ks = 0; ks < 32; ks += 16) {
            // B fragments: 8 n-frags of 8 cols via 4 ldsm4
            unsigned bh[8][2];
            #pragma unroll
            for (int nip = 0; nip < 4; nip++) {
                const int nf = wn + nip * 16;
                unsigned off;
                if (B_T) {
                    off = bBase + (ks + la7 + 8 * la_b3) * 272 + (nf + 8 * la_hi4) * 2;
                } else {
                    off = bBase + (nf + la7 + 8 * la_hi4) * 80 + (ks + 8 * la_b3) * 2;
                }
                unsigned r[4];
                ldsm4<B_T>(r, off);
                bh[nip*2][0] = r[0]; bh[nip*2][1] = r[1];
                bh[nip*2+1][0] = r[2]; bh[nip*2+1][1] = r[3];
            }
            #pragma unroll
            for (int mi = 0; mi < 4; mi++) {
                const int mf = wm + mi * 16;
                unsigned ah[4], al[4];
                unsigned off;
                if (A_T) {
                    off = aBase + (ks + la7 + 8 * la_hi4) * 272 + (mf + 8 * la_b3) * 2;
                } else {
                    off = aBase + (mf + la15) * 80 + (ks + 8 * la_hi4) * 2;
                }
                ldsm4<A_T>(ah, off);
                ldsm4<A_T>(al, off + A_PB);
                #pragma unroll
                for (int ni = 0; ni < 8; ni++) {
                    mma_f16(acc[mi][ni], ah, bh[ni]);   // hi * B
                    mma_f16(acc[mi][ni], al, bh[ni]);   // lo * B
                }
            }
        }
    }

    // ---- epilogue ----
    #pragma unroll
    for (int mi = 0; mi < 4; mi++) {
        #pragma unroll
        for (int half = 0; half < 2; half++) {
            const int row = m0 + wm + mi * 16 + gid + half * 8;
            const float bv = (OUTM == 1 || OUTM == 2) ? bias[row] : 0.f;
            #pragma unroll
            for (int ni = 0; ni < 8; ni++) {
                const int col = n0 + wn + ni * 8 + tid4 * 2;
                float v0 = acc[mi][ni][half * 2 + 0] * alpha + bv;
                float v1 = acc[mi][ni][half * 2 + 1] * alpha + bv;
                const size_t off = (size_t)row * N + col;
                if (OUTM == 0) {
                    *(float2*)&C[off] = make_float2(v0, v1);
                } else if (OUTM == 1) {
                    const float* rp = res + off;
                    *(float2*)&C[off] = make_float2(v0 + rp[0], v1 + rp[1]);
                } else if (OUTM == 2) {
                    __half h0, l0, h1, l1;
                    split2h(v0, h0, l0); split2h(v1, h1, l1);
                    *(__half2*)&Chi[off] = __halves2half2(h0, h1);
                    *(__half2*)&Clo[off] = __halves2half2(l0, l1);
                } else {
                    *(__half2*)&Chi[off] = __floats2half2_rn(v0, v1);
                }
            }
        }
    }
}

// ---------------------------------------------------------------------------
// Row softmax over 1024 elements + single fp16 plane output (attn is B-only).
// ---------------------------------------------------------------------------
__global__ void softmax_k(const float* __restrict__ S) {
    const size_t row = blockIdx.x;
    const float4* p = (const float4*)(S + row * (size_t)NPIX);
    float4 v = p[threadIdx.x];

    __shared__ float sh[8];
    __shared__ float bcast;

    float mx = fmaxf(fmaxf(v.x, v.y), fmaxf(v.z, v.w));
    mx = warp_max(mx);
    if (!(threadIdx.x & 31)) sh[threadIdx.x >> 5] = mx;
    __syncthreads();
    if (threadIdx.x < 32) {
        float t = (threadIdx.x < 8) ? sh[threadIdx.x] : -1e30f;
        t = warp_max(t);
        if (!threadIdx.x) bcast = t;
    }
    __syncthreads();
    mx = bcast;
    __syncthreads();

    v.x = __expf(v.x - mx); v.y = __expf(v.y - mx);
    v.z = __expf(v.z - mx); v.w = __expf(v.w - mx);
    float s = v.x + v.y + v.z + v.w;
    s = warp_sum(s);
    if (!(threadIdx.x & 31)) sh[threadIdx.x >> 5] = s;
    __syncthreads();
    if (threadIdx.x < 32) {
        float t = (threadIdx.x < 8) ? sh[threadIdx.x] : 0.f;
        t = warp_sum(t);
        if (!threadIdx.x) bcast = t;
    }
    __syncthreads();
    const float inv = 1.f / bcast;
    const size_t i2 = row * (NPIX / 2) + threadIdx.x * 2;
    ((__half2*)g_attb)[i2 + 0] = __floats2half2_rn(v.x * inv, v.y * inv);
    ((__half2*)g_attb)[i2 + 1] = __floats2half2_rn(v.z * inv, v.w * inv);
}

// ---------------------------------------------------------------------------
// Launch
// ---------------------------------------------------------------------------
extern "C" void kernel_launch(void* const* d_in, const int* in_sizes, int n_in,
                              void* d_out, int out_size) {
    const float* x  = (const float*)d_in[0];
    const float* nw = (const float*)d_in[1];
    const float* nb = (const float*)d_in[2];
    const float* qw = (const float*)d_in[3];
    const float* qb = (const float*)d_in[4];
    const float* pw = (const float*)d_in[5];
    const float* pb = (const float*)d_in[6];
    float* out = (float*)d_out;

    __half *wq0, *wq1, *wp0, *wp1, *hb, *qk0, *qk1, *at, *ho;
    float* attn;
    cudaGetSymbolAddress((void**)&wq0, g_wq);   wq1 = wq0 + (size_t)3*CH*CH;
    cudaGetSymbolAddress((void**)&wp0, g_wp);   wp1 = wp0 + (size_t)CH*CH;
    cudaGetSymbolAddress((void**)&hb,  g_hb);
    cudaGetSymbolAddress((void**)&qk0, g_qkvb); qk1 = qk0 + (size_t)BATCH*3*CH*NPIX;
    cudaGetSymbolAddress((void**)&at,  g_attb);
    cudaGetSymbolAddress((void**)&ho,  g_houtb);
    cudaGetSymbolAddress((void**)&attn, g_attn);

    const size_t sH   = (size_t)CH * NPIX;
    const size_t sQKV = (size_t)3 * CH * NPIX;
    const size_t sAT  = (size_t)NPIX * NPIX;

    // 3-stage dynamic smem sizes (fp16): A plane: A_T? 8704:10240; B same formula
    const int SM_QKV = 3 * (2*10240 + 8704);    // 87552  (A=false, B_T=true)
    const int SM_SC  = 3 * (2*8704  + 8704);    // 78336  (A_T, B_T)
    const int SM_AV  = 3 * (2*10240 + 10240);   // 92160  (A=false, B=false)
    const int SM_PR  = SM_QKV;                  // proj same shape as QKV

    cudaFuncSetAttribute(gemm_h<false,true ,2>, cudaFuncAttributeMaxDynamicSharedMemorySize, SM_QKV);
    cudaFuncSetAttribute(gemm_h<true ,true ,0>, cudaFuncAttributeMaxDynamicSharedMemorySize, SM_SC);
    cudaFuncSetAttribute(gemm_h<false,false,3>, cudaFuncAttributeMaxDynamicSharedMemorySize, SM_AV);
    cudaFuncSetAttribute(gemm_h<false,true ,1>, cudaFuncAttributeMaxDynamicSharedMemorySize, SM_PR);

    // 0) split weights to fp16 hi/lo
    wsplit_k<<<(3*CH*CH)/(4*256), 256>>>(qw, wq0, wq1);
    wsplit_k<<<(CH*CH)/(4*256), 256>>>(pw, wp0, wp1);

    // 1) GroupNorm (writes single-plane h)
    gn_stats_k<<<BATCH * NGRP, 256>>>(x);
    gn_apply_k<<<(BATCH * CH * NPIX) / (4 * 256), 256>>>(x, nw, nb);

    // 2) QKV = qkv_w @ h + qkv_b  (M=1536,N=1024,K=512)  A:[M][K] split, B:[K][N]
    gemm_h<false,true,2><<<dim3(8,12,BATCH), 128, SM_QKV>>>(
        wq0, wq1, hb, nullptr, qk0, qk1, qb, nullptr,
        3*CH, NPIX, CH, CH, NPIX, 0, sH, sQKV, 1.f);

    // 3) scores[n][m] = scale * sum_c q[c][n] k[c][m]  (M=N=1024,K=512)
    //    A = q (hi+lo planes, [K][M]), B = k (hi plane, [K][N])
    const float scale = 0.044194173824159216f;
    gemm_h<true,true,0><<<dim3(8,8,BATCH), 128, SM_SC>>>(
        qk0, qk1, qk0 + sH, attn, nullptr, nullptr, nullptr, nullptr,
        NPIX, NPIX, CH, NPIX, NPIX, sQKV, sQKV, sAT, scale);

    // 4) softmax rows (single-plane fp16 out)
    softmax_k<<<BATCH * NPIX, 256>>>(attn);

    // 5) hout[c][n] = sum_m v[c][m] attn[n][m]  (M=512,N=1024,K=1024)
    //    A = v (hi+lo, [M][K]), B = attn (hi, [N][K]) -> single-plane out
    gemm_h<false,false,3><<<dim3(8,4,BATCH), 128, SM_AV>>>(
        qk0 + 2*sH, qk1 + 2*sH, at, nullptr, ho, nullptr, nullptr, nullptr,
        CH, NPIX, NPIX, NPIX, NPIX, sQKV, sAT, sH, 1.f);

    // 6) out = x + proj_w @ hout + proj_b  (M=512,N=1024,K=512)
    gemm_h<false,true,1><<<dim3(8,4,BATCH), 128, SM_PR>>>(
        wp0, wp1, ho, out, nullptr, nullptr, pb, x,
        CH, NPIX, CH, CH, NPIX, 0, sH, sH, 1.f);
}

// round 12
// speedup vs baseline: 6.4566x; 1.7059x over previous
#include <cuda_runtime.h>
#include <cuda_fp16.h>

// Problem constants
#define BATCH 32
#define CH    512
#define NPIX  1024   // H*W = 32*32
#define NGRP  32
#define CPG   16     // channels per group

// ---------------------------------------------------------------------------
// Scratch (device globals — no allocations allowed)
// ---------------------------------------------------------------------------
__device__ float g_mean[BATCH * NGRP];
__device__ float g_rstd[BATCH * NGRP];

// Single fp16 plane per tensor (pure fp16 GEMM operands)
__device__ __half g_wq   [(size_t)3 * CH * CH];                 // qkv_w
__device__ __half g_wp   [(size_t)CH * CH];                     // proj_w
__device__ __half g_hb   [(size_t)BATCH * CH * NPIX];           // groupnorm out
__device__ __half g_qkvb [(size_t)BATCH * 3 * CH * NPIX];       // qkv out
__device__ __half g_attb [(size_t)BATCH * NPIX * NPIX];         // softmax out
__device__ __half g_houtb[(size_t)BATCH * CH * NPIX];           // attn*V out
__device__ float g_attn[(size_t)BATCH * NPIX * NPIX];           // scores (fp32)

// ---------------------------------------------------------------------------
// Helpers
// ---------------------------------------------------------------------------
__device__ __forceinline__ float warp_sum(float v) {
    #pragma unroll
    for (int o = 16; o; o >>= 1) v += __shfl_xor_sync(0xffffffffu, v, o);
    return v;
}
__device__ __forceinline__ float warp_max(float v) {
    #pragma unroll
    for (int o = 16; o; o >>= 1) v = fmaxf(v, __shfl_xor_sync(0xffffffffu, v, o));
    return v;
}

__device__ __forceinline__ void mma_f16(float* d, const unsigned* a, const unsigned* b) {
    asm volatile(
        "mma.sync.aligned.m16n8k16.row.col.f32.f16.f16.f32 "
        "{%0,%1,%2,%3}, {%4,%5,%6,%7}, {%8,%9}, {%0,%1,%2,%3};"
        : "+f"(d[0]), "+f"(d[1]), "+f"(d[2]), "+f"(d[3])
        : "r"(a[0]), "r"(a[1]), "r"(a[2]), "r"(a[3]),
          "r"(b[0]), "r"(b[1]));
}

template<bool T>
__device__ __forceinline__ void ldsm4(unsigned r[4], unsigned addr) {
    if (T)
        asm volatile("ldmatrix.sync.aligned.m8n8.x4.trans.shared.b16 {%0,%1,%2,%3}, [%4];"
                     : "=r"(r[0]), "=r"(r[1]), "=r"(r[2]), "=r"(r[3]) : "r"(addr));
    else
        asm volatile("ldmatrix.sync.aligned.m8n8.x4.shared.b16 {%0,%1,%2,%3}, [%4];"
                     : "=r"(r[0]), "=r"(r[1]), "=r"(r[2]), "=r"(r[3]) : "r"(addr));
}

__device__ __forceinline__ void cp16(unsigned dst, const void* src) {
    asm volatile("cp.async.cg.shared.global [%0], [%1], 16;" :: "r"(dst), "l"(src));
}
__device__ __forceinline__ void cp_commit() { asm volatile("cp.async.commit_group;"); }

// ---------------------------------------------------------------------------
// Weight round kernel (fp32 -> fp16 single plane)
// ---------------------------------------------------------------------------
__global__ void wround_k(const float* __restrict__ src, __half* __restrict__ dst) {
    const int i4 = blockIdx.x * 256 + threadIdx.x;
    float4 v = ((const float4*)src)[i4];
    ((__half2*)dst)[i4*2+0] = __floats2half2_rn(v.x, v.y);
    ((__half2*)dst)[i4*2+1] = __floats2half2_rn(v.z, v.w);
}

// ---------------------------------------------------------------------------
// GroupNorm
// ---------------------------------------------------------------------------
__global__ void gn_stats_k(const float* __restrict__ x) {
    const int bg = blockIdx.x;
    const float4* p = (const float4*)(x + (size_t)bg * (CPG * NPIX));
    float s = 0.f, ss = 0.f;
    for (int i = threadIdx.x; i < (CPG * NPIX) / 4; i += 256) {
        float4 v = p[i];
        s  += v.x + v.y + v.z + v.w;
        ss += v.x * v.x + v.y * v.y + v.z * v.z + v.w * v.w;
    }
    __shared__ float sh1[8], sh2[8];
    s = warp_sum(s); ss = warp_sum(ss);
    const int w = threadIdx.x >> 5, l = threadIdx.x & 31;
    if (!l) { sh1[w] = s; sh2[w] = ss; }
    __syncthreads();
    if (threadIdx.x < 32) {
        float a = (threadIdx.x < 8) ? sh1[threadIdx.x] : 0.f;
        float b = (threadIdx.x < 8) ? sh2[threadIdx.x] : 0.f;
        a = warp_sum(a); b = warp_sum(b);
        if (!threadIdx.x) {
            const float inv_n = 1.f / (float)(CPG * NPIX);
            float m   = a * inv_n;
            float var = b * inv_n - m * m;
            g_mean[bg] = m;
            g_rstd[bg] = rsqrtf(var + 1e-5f);
        }
    }
}

__global__ void gn_apply_k(const float* __restrict__ x,
                           const float* __restrict__ w,
                           const float* __restrict__ b) {
    const int idx4 = blockIdx.x * 256 + threadIdx.x;
    const int c  = (idx4 >> 8) & (CH - 1);
    const int bb = idx4 >> 17;
    const int bg = bb * NGRP + (c >> 4);
    const float m = g_mean[bg], r = g_rstd[bg];
    const float sc = r * w[c];
    const float sh = b[c] - m * sc;
    float4 v = ((const float4*)x)[idx4];
    ((__half2*)g_hb)[idx4*2+0] = __floats2half2_rn(v.x*sc+sh, v.y*sc+sh);
    ((__half2*)g_hb)[idx4*2+1] = __floats2half2_rn(v.z*sc+sh, v.w*sc+sh);
}

// ---------------------------------------------------------------------------
// Batched fp16 tensor-core GEMM, 4-stage cp.async pipeline, ldmatrix x4.
//   logical C[m][n] = alpha * sum_k A(m,k)*B(k,n)
//   A_T: A source stored [K][M] (ld=lda), smem [k][m], ldmatrix.trans
//   B_T: B source stored [K][N] (ld=ldb), smem [k][n], ldmatrix.trans
//   OUTM: 0 = fp32*alpha | 1 = fp32 + bias[row] + res
//         2 = fp16 + bias[row] | 3 = fp16
// CTA tile 128x128x32, 128 threads (2x2 warps), warp tile 64x64, m16n8k16.
// All dims multiples of tile sizes. K/32 >= 4.
// ---------------------------------------------------------------------------
template<bool A_T, bool B_T, int OUTM>
__global__ void __launch_bounds__(128, 2) gemm_h(
    const __half* __restrict__ A, const __half* __restrict__ B,
    float* __restrict__ C, __half* __restrict__ Ch,
    const float* __restrict__ bias, const float* __restrict__ res,
    int M, int N, int K, int lda, int ldb,
    size_t sA, size_t sB, size_t sC, float alpha)
{
    // per-tile smem bytes (row-pitch padded: 40 h / 136 h)
    constexpr int A_PB  = (A_T ? 32 * 136 : 128 * 40) * 2;
    constexpr int B_PB  = (B_T ? 32 * 136 : 128 * 40) * 2;
    constexpr int STAGE = A_PB + B_PB;

    extern __shared__ char smem[];
    const unsigned sbase = (unsigned)__cvta_generic_to_shared(smem);

    const int bz = blockIdx.z;
    A += sA * bz; B += sB * bz;
    if (OUTM == 0 || OUTM == 1) { C += sC * bz; if (OUTM == 1) res += sC * bz; }
    else Ch += sC * bz;

    const int tid = threadIdx.x;
    const int m0 = blockIdx.y * 128, n0 = blockIdx.x * 128;
    const int wid = tid >> 5, lane = tid & 31;
    const int wm = (wid >> 1) * 64;     // warp rows: 0 / 64
    const int wn = (wid & 1) * 64;      // warp cols: 0 / 64
    const int gid = lane >> 2, tid4 = lane & 3;

    float acc[4][8][4];
    #pragma unroll
    for (int mi = 0; mi < 4; mi++)
        #pragma unroll
        for (int ni = 0; ni < 8; ni++)
            #pragma unroll
            for (int j = 0; j < 4; j++) acc[mi][ni][j] = 0.f;

    // ---- async stage loader: A 512 chunks + B 512 chunks, 128 threads ----
    auto load_stage = [&](int st, int kt) {
        const unsigned base = sbase + st * STAGE;
        #pragma unroll
        for (int c = tid; c < 512; c += 128) {
            if (A_T) {
                const int row = c >> 4, seg = c & 15;
                cp16(base + row * 272 + seg * 16,
                     A + (size_t)(kt + row) * lda + m0 + seg * 8);
            } else {
                const int row = c >> 2, seg = c & 3;
                cp16(base + row * 80 + seg * 16,
                     A + (size_t)(m0 + row) * lda + kt + seg * 8);
            }
        }
        #pragma unroll
        for (int c = tid; c < 512; c += 128) {
            if (B_T) {
                const int row = c >> 4, seg = c & 15;
                cp16(base + A_PB + row * 272 + seg * 16,
                     B + (size_t)(kt + row) * ldb + n0 + seg * 8);
            } else {
                const int row = c >> 2, seg = c & 3;
                cp16(base + A_PB + row * 80 + seg * 16,
                     B + (size_t)(n0 + row) * ldb + kt + seg * 8);
            }
        }
    };

    const int la15 = lane & 15, la7 = lane & 7;
    const int la_hi4 = lane >> 4, la_b3 = (lane >> 3) & 1;

    const int T = K / 32;   // >= 4 for all our shapes (min K=512 -> 16)
    load_stage(0, 0);  cp_commit();
    load_stage(1, 32); cp_commit();
    load_stage(2, 64); cp_commit();

    for (int t = 0; t < T; t++) {
        asm volatile("cp.async.wait_group 2;");   // stage t complete
        __syncthreads();                          // fences reuse of slot (t+3)&3
        if (t + 3 < T) load_stage((t + 3) & 3, (t + 3) * 32);
        cp_commit();                              // uniform group accounting

        const unsigned aBase = sbase + (t & 3) * STAGE;
        const unsigned bBase = aBase + A_PB;

        #pragma unroll
        for (int ks = 0; ks < 32; ks += 16) {
            // B fragments: 8 n-frags of 8 cols via 4 ldsm4
            unsigned bh[8][2];
            #pragma unroll
            for (int nip = 0; nip < 4; nip++) {
                const int nf = wn + nip * 16;
                unsigned off;
                if (B_T) {
                    off = bBase + (ks + la7 + 8 * la_b3) * 272 + (nf + 8 * la_hi4) * 2;
                } else {
                    off = bBase + (nf + la7 + 8 * la_hi4) * 80 + (ks + 8 * la_b3) * 2;
                }
                unsigned r[4];
                ldsm4<B_T>(r, off);
                bh[nip*2][0] = r[0]; bh[nip*2][1] = r[1];
                bh[nip*2+1][0] = r[2]; bh[nip*2+1][1] = r[3];
            }
            #pragma unroll
            for (int mi = 0; mi < 4; mi++) {
                const int mf = wm + mi * 16;
                unsigned ah[4];
                unsigned off;
                if (A_T) {
                    off = aBase + (ks + la7 + 8 * la_hi4) * 272 + (mf + 8 * la_b3) * 2;
                } else {
                    off = aBase + (mf + la15) * 80 + (ks + 8 * la_hi4) * 2;
                }
                ldsm4<A_T>(ah, off);
                #pragma unroll
                for (int ni = 0; ni < 8; ni++)
                    mma_f16(acc[mi][ni], ah, bh[ni]);
            }
        }
    }

    // ---- epilogue ----
    #pragma unroll
    for (int mi = 0; mi < 4; mi++) {
        #pragma unroll
        for (int half = 0; half < 2; half++) {
            const int row = m0 + wm + mi * 16 + gid + half * 8;
            const float bv = (OUTM == 1 || OUTM == 2) ? bias[row] : 0.f;
            #pragma unroll
            for (int ni = 0; ni < 8; ni++) {
                const int col = n0 + wn + ni * 8 + tid4 * 2;
                float v0 = acc[mi][ni][half * 2 + 0] * alpha + bv;
                float v1 = acc[mi][ni][half * 2 + 1] * alpha + bv;
                const size_t off = (size_t)row * N + col;
                if (OUTM == 0) {
                    *(float2*)&C[off] = make_float2(v0, v1);
                } else if (OUTM == 1) {
                    const float* rp = res + off;
                    *(float2*)&C[off] = make_float2(v0 + rp[0], v1 + rp[1]);
                } else {
                    *(__half2*)&Ch[off] = __floats2half2_rn(v0, v1);
                }
            }
        }
    }
}

// ---------------------------------------------------------------------------
// Row softmax over 1024 elements + fp16 output.
// ---------------------------------------------------------------------------
__global__ void softmax_k(const float* __restrict__ S) {
    const size_t row = blockIdx.x;
    const float4* p = (const float4*)(S + row * (size_t)NPIX);
    float4 v = p[threadIdx.x];

    __shared__ float sh[8];
    __shared__ float bcast;

    float mx = fmaxf(fmaxf(v.x, v.y), fmaxf(v.z, v.w));
    mx = warp_max(mx);
    if (!(threadIdx.x & 31)) sh[threadIdx.x >> 5] = mx;
    __syncthreads();
    if (threadIdx.x < 32) {
        float t = (threadIdx.x < 8) ? sh[threadIdx.x] : -1e30f;
        t = warp_max(t);
        if (!threadIdx.x) bcast = t;
    }
    __syncthreads();
    mx = bcast;
    __syncthreads();

    v.x = __expf(v.x - mx); v.y = __expf(v.y - mx);
    v.z = __expf(v.z - mx); v.w = __expf(v.w - mx);
    float s = v.x + v.y + v.z + v.w;
    s = warp_sum(s);
    if (!(threadIdx.x & 31)) sh[threadIdx.x >> 5] = s;
    __syncthreads();
    if (threadIdx.x < 32) {
        float t = (threadIdx.x < 8) ? sh[threadIdx.x] : 0.f;
        t = warp_sum(t);
        if (!threadIdx.x) bcast = t;
    }
    __syncthreads();
    const float inv = 1.f / bcast;
    const size_t i2 = row * (NPIX / 2) + threadIdx.x * 2;
    ((__half2*)g_attb)[i2 + 0] = __floats2half2_rn(v.x * inv, v.y * inv);
    ((__half2*)g_attb)[i2 + 1] = __floats2half2_rn(v.z * inv, v.w * inv);
}

// ---------------------------------------------------------------------------
// Launch
// ---------------------------------------------------------------------------
extern "C" void kernel_launch(void* const* d_in, const int* in_sizes, int n_in,
                              void* d_out, int out_size) {
    const float* x  = (const float*)d_in[0];
    const float* nw = (const float*)d_in[1];
    const float* nb = (const float*)d_in[2];
    const float* qw = (const float*)d_in[3];
    const float* qb = (const float*)d_in[4];
    const float* pw = (const float*)d_in[5];
    const float* pb = (const float*)d_in[6];
    float* out = (float*)d_out;

    __half *wq, *wp, *hb, *qk, *at, *ho;
    float* attn;
    cudaGetSymbolAddress((void**)&wq, g_wq);
    cudaGetSymbolAddress((void**)&wp, g_wp);
    cudaGetSymbolAddress((void**)&hb, g_hb);
    cudaGetSymbolAddress((void**)&qk, g_qkvb);
    cudaGetSymbolAddress((void**)&at, g_attb);
    cudaGetSymbolAddress((void**)&ho, g_houtb);
    cudaGetSymbolAddress((void**)&attn, g_attn);

    const size_t sH   = (size_t)CH * NPIX;
    const size_t sQKV = (size_t)3 * CH * NPIX;
    const size_t sAT  = (size_t)NPIX * NPIX;

    // 4-stage dynamic smem: A tile (A_T? 8704:10240) + B tile (same formula)
    const int SM_QKV = 4 * (10240 + 8704);   // 75776  (A=false, B_T=true)
    const int SM_SC  = 4 * (8704 + 8704);    // 69632  (A_T, B_T)
    const int SM_AV  = 4 * (10240 + 10240);  // 81920  (A=false, B=false)
    const int SM_PR  = SM_QKV;

    cudaFuncSetAttribute(gemm_h<false,true ,2>, cudaFuncAttributeMaxDynamicSharedMemorySize, SM_QKV);
    cudaFuncSetAttribute(gemm_h<true ,true ,0>, cudaFuncAttributeMaxDynamicSharedMemorySize, SM_SC);
    cudaFuncSetAttribute(gemm_h<false,false,3>, cudaFuncAttributeMaxDynamicSharedMemorySize, SM_AV);
    cudaFuncSetAttribute(gemm_h<false,true ,1>, cudaFuncAttributeMaxDynamicSharedMemorySize, SM_PR);

    // 0) round weights to fp16
    wround_k<<<(3*CH*CH)/(4*256), 256>>>(qw, wq);
    wround_k<<<(CH*CH)/(4*256), 256>>>(pw, wp);

    // 1) GroupNorm (fp16 h)
    gn_stats_k<<<BATCH * NGRP, 256>>>(x);
    gn_apply_k<<<(BATCH * CH * NPIX) / (4 * 256), 256>>>(x, nw, nb);

    // 2) QKV = qkv_w @ h + qkv_b  (M=1536,N=1024,K=512)  A:[M][K], B:[K][N]
    gemm_h<false,true,2><<<dim3(8,12,BATCH), 128, SM_QKV>>>(
        wq, hb, nullptr, qk, qb, nullptr,
        3*CH, NPIX, CH, CH, NPIX, 0, sH, sQKV, 1.f);

    // 3) scores[n][m] = scale * sum_c q[c][n] k[c][m]  (M=N=1024,K=512)
    const float scale = 0.044194173824159216f;
    gemm_h<true,true,0><<<dim3(8,8,BATCH), 128, SM_SC>>>(
        qk, qk + sH, attn, nullptr, nullptr, nullptr,
        NPIX, NPIX, CH, NPIX, NPIX, sQKV, sQKV, sAT, scale);

    // 4) softmax rows (fp16 out)
    softmax_k<<<BATCH * NPIX, 256>>>(attn);

    // 5) hout[c][n] = sum_m v[c][m] attn[n][m]  (M=512,N=1024,K=1024)
    //    A = v [M][K], B = attn [N][K]
    gemm_h<false,false,3><<<dim3(8,4,BATCH), 128, SM_AV>>>(
        qk + 2*sH, at, nullptr, ho, nullptr, nullptr,
        CH, NPIX, NPIX, NPIX, NPIX, sQKV, sAT, sH, 1.f);

    // 6) out = x + proj_w @ hout + proj_b  (M=512,N=1024,K=512)
    gemm_h<false,true,1><<<dim3(8,4,BATCH), 128, SM_PR>>>(
        wp, ho, out, nullptr, pb, x,
        CH, NPIX, CH, CH, NPIX, 0, sH, sH, 1.f);
}

// round 14
// speedup vs baseline: 6.4574x; 1.0001x over previous
#include <cuda_runtime.h>
#include <cuda_fp16.h>

// Problem constants
#define BATCH 32
#define CH    512
#define NPIX  1024   // H*W = 32*32
#define NGRP  32
#define CPG   16     // channels per group

// ---------------------------------------------------------------------------
// Scratch (device globals — no allocations allowed)
// ---------------------------------------------------------------------------
__device__ __half g_wq   [(size_t)3 * CH * CH];                 // qkv_w
__device__ __half g_wp   [(size_t)CH * CH];                     // proj_w
__device__ __half g_hb   [(size_t)BATCH * CH * NPIX];           // groupnorm out
__device__ __half g_qkvb [(size_t)BATCH * 3 * CH * NPIX];       // qkv out
__device__ __half g_attb [(size_t)BATCH * NPIX * NPIX];         // softmax out
__device__ __half g_houtb[(size_t)BATCH * CH * NPIX];           // attn*V out
__device__ float g_attn[(size_t)BATCH * NPIX * NPIX];           // scores (fp32)

// ---------------------------------------------------------------------------
// Helpers
// ---------------------------------------------------------------------------
__device__ __forceinline__ float warp_sum(float v) {
    #pragma unroll
    for (int o = 16; o; o >>= 1) v += __shfl_xor_sync(0xffffffffu, v, o);
    return v;
}
__device__ __forceinline__ float warp_max(float v) {
    #pragma unroll
    for (int o = 16; o; o >>= 1) v = fmaxf(v, __shfl_xor_sync(0xffffffffu, v, o));
    return v;
}

__device__ __forceinline__ void mma_f16(float* d, const unsigned* a, const unsigned* b) {
    asm volatile(
        "mma.sync.aligned.m16n8k16.row.col.f32.f16.f16.f32 "
        "{%0,%1,%2,%3}, {%4,%5,%6,%7}, {%8,%9}, {%0,%1,%2,%3};"
        : "+f"(d[0]), "+f"(d[1]), "+f"(d[2]), "+f"(d[3])
        : "r"(a[0]), "r"(a[1]), "r"(a[2]), "r"(a[3]),
          "r"(b[0]), "r"(b[1]));
}

template<bool T>
__device__ __forceinline__ void ldsm4(unsigned r[4], unsigned addr) {
    if (T)
        asm volatile("ldmatrix.sync.aligned.m8n8.x4.trans.shared.b16 {%0,%1,%2,%3}, [%4];"
                     : "=r"(r[0]), "=r"(r[1]), "=r"(r[2]), "=r"(r[3]) : "r"(addr));
    else
        asm volatile("ldmatrix.sync.aligned.m8n8.x4.shared.b16 {%0,%1,%2,%3}, [%4];"
                     : "=r"(r[0]), "=r"(r[1]), "=r"(r[2]), "=r"(r[3]) : "r"(addr));
}

__device__ __forceinline__ void cp16(unsigned dst, const void* src) {
    asm volatile("cp.async.cg.shared.global [%0], [%1], 16;" :: "r"(dst), "l"(src));
}
__device__ __forceinline__ void cp_commit() { asm volatile("cp.async.commit_group;"); }

// ---------------------------------------------------------------------------
// Weight round kernel (fp32 -> fp16)
// ---------------------------------------------------------------------------
__global__ void wround_k(const float* __restrict__ src, __half* __restrict__ dst) {
    const int i4 = blockIdx.x * 256 + threadIdx.x;
    float4 v = ((const float4*)src)[i4];
    ((__half2*)dst)[i4*2+0] = __floats2half2_rn(v.x, v.y);
    ((__half2*)dst)[i4*2+1] = __floats2half2_rn(v.z, v.w);
}

// ---------------------------------------------------------------------------
// Fused GroupNorm: one block per (batch, group). Slab = 16 ch * 1024 pix,
// contiguous 64KB. Pass 1: stats (reads, mostly L1/L2-resident after).
// Pass 2: normalize + fp16 write.
// ---------------------------------------------------------------------------
__global__ void gn_fused_k(const float* __restrict__ x,
                           const float* __restrict__ w,
                           const float* __restrict__ b) {
    const int bg = blockIdx.x;                       // b*32 + g
    const float4* p = (const float4*)(x + (size_t)bg * (CPG * NPIX));
    float s = 0.f, ss = 0.f;
    #pragma unroll 4
    for (int i = threadIdx.x; i < (CPG * NPIX) / 4; i += 256) {
        float4 v = p[i];
        s  += v.x + v.y + v.z + v.w;
        ss += v.x * v.x + v.y * v.y + v.z * v.z + v.w * v.w;
    }
    __shared__ float sh1[8], sh2[8];
    __shared__ float s_mean, s_rstd;
    s = warp_sum(s); ss = warp_sum(ss);
    const int wi = threadIdx.x >> 5, l = threadIdx.x & 31;
    if (!l) { sh1[wi] = s; sh2[wi] = ss; }
    __syncthreads();
    if (threadIdx.x < 32) {
        float a = (threadIdx.x < 8) ? sh1[threadIdx.x] : 0.f;
        float c = (threadIdx.x < 8) ? sh2[threadIdx.x] : 0.f;
        a = warp_sum(a); c = warp_sum(c);
        if (!threadIdx.x) {
            const float inv_n = 1.f / (float)(CPG * NPIX);
            float m   = a * inv_n;
            float var = c * inv_n - m * m;
            s_mean = m;
            s_rstd = rsqrtf(var + 1e-5f);
        }
    }
    __syncthreads();
    const float m = s_mean, r = s_rstd;
    const int g16 = (bg & (NGRP - 1)) * CPG;         // first channel of group
    __half2* dst = (__half2*)(g_hb + (size_t)bg * (CPG * NPIX));
    #pragma unroll 4
    for (int i = threadIdx.x; i < (CPG * NPIX) / 4; i += 256) {
        const int c = g16 + (i >> 8);                // 256 f4 per channel
        const float sc = r * w[c];
        const float sh = b[c] - m * sc;
        float4 v = p[i];
        dst[i*2+0] = __floats2half2_rn(v.x*sc+sh, v.y*sc+sh);
        dst[i*2+1] = __floats2half2_rn(v.z*sc+sh, v.w*sc+sh);
    }
}

// ---------------------------------------------------------------------------
// Batched fp16 tensor-core GEMM, 4-stage cp.async pipeline, ldmatrix x4,
// double-buffered fragments (both k-steps loaded before MMA block).
//   logical C[m][n] = alpha * sum_k A(m,k)*B(k,n)
//   A_T: A source stored [K][M] (ld=lda), smem [k][m], ldmatrix.trans
//   B_T: B source stored [K][N] (ld=ldb), smem [k][n], ldmatrix.trans
//   OUTM: 0 = fp32*alpha | 1 = fp32 + bias[row] + res
//         2 = fp16 + bias[row] | 3 = fp16
// CTA tile 128x128x32, 128 threads (2x2 warps), warp tile 64x64, m16n8k16.
// All dims multiples of tile sizes. K/32 >= 4.
// ---------------------------------------------------------------------------
template<bool A_T, bool B_T, int OUTM>
__global__ void __launch_bounds__(128, 2) gemm_h(
    const __half* __restrict__ A, const __half* __restrict__ B,
    float* __restrict__ C, __half* __restrict__ Ch,
    const float* __restrict__ bias, const float* __restrict__ res,
    int M, int N, int K, int lda, int ldb,
    size_t sA, size_t sB, size_t sC, float alpha)
{
    // per-tile smem bytes (row-pitch padded: 40 h / 136 h)
    constexpr int A_PB  = (A_T ? 32 * 136 : 128 * 40) * 2;
    constexpr int B_PB  = (B_T ? 32 * 136 : 128 * 40) * 2;
    constexpr int STAGE = A_PB + B_PB;

    extern __shared__ char smem[];
    const unsigned sbase = (unsigned)__cvta_generic_to_shared(smem);

    const int bz = blockIdx.z;
    A += sA * bz; B += sB * bz;
    if (OUTM == 0 || OUTM == 1) { C += sC * bz; if (OUTM == 1) res += sC * bz; }
    else Ch += sC * bz;

    const int tid = threadIdx.x;
    const int m0 = blockIdx.y * 128, n0 = blockIdx.x * 128;
    const int wid = tid >> 5, lane = tid & 31;
    const int wm = (wid >> 1) * 64;     // warp rows: 0 / 64
    const int wn = (wid & 1) * 64;      // warp cols: 0 / 64
    const int gid = lane >> 2, tid4 = lane & 3;

    float acc[4][8][4];
    #pragma unroll
    for (int mi = 0; mi < 4; mi++)
        #pragma unroll
        for (int ni = 0; ni < 8; ni++)
            #pragma unroll
            for (int j = 0; j < 4; j++) acc[mi][ni][j] = 0.f;

    // ---- async stage loader: A 512 chunks + B 512 chunks, 128 threads ----
    auto load_stage = [&](int st, int kt) {
        const unsigned base = sbase + st * STAGE;
        #pragma unroll
        for (int c = tid; c < 512; c += 128) {
            if (A_T) {
                const int row = c >> 4, seg = c & 15;
                cp16(base + row * 272 + seg * 16,
                     A + (size_t)(kt + row) * lda + m0 + seg * 8);
            } else {
                const int row = c >> 2, seg = c & 3;
                cp16(base + row * 80 + seg * 16,
                     A + (size_t)(m0 + row) * lda + kt + seg * 8);
            }
        }
        #pragma unroll
        for (int c = tid; c < 512; c += 128) {
            if (B_T) {
                const int row = c >> 4, seg = c & 15;
                cp16(base + A_PB + row * 272 + seg * 16,
                     B + (size_t)(kt + row) * ldb + n0 + seg * 8);
            } else {
                const int row = c >> 2, seg = c & 3;
                cp16(base + A_PB + row * 80 + seg * 16,
                     B + (size_t)(n0 + row) * ldb + kt + seg * 8);
            }
        }
    };

    const int la15 = lane & 15, la7 = lane & 7;
    const int la_hi4 = lane >> 4, la_b3 = (lane >> 3) & 1;

    const int T = K / 32;   // >= 4 for all our shapes
    load_stage(0, 0);  cp_commit();
    load_stage(1, 32); cp_commit();
    load_stage(2, 64); cp_commit();

    for (int t = 0; t < T; t++) {
        asm volatile("cp.async.wait_group 2;");   // stage t complete
        __syncthreads();                          // fences reuse of slot (t+3)&3
        if (t + 3 < T) load_stage((t + 3) & 3, (t + 3) * 32);
        cp_commit();                              // uniform group accounting

        const unsigned aBase = sbase + (t & 3) * STAGE;
        const unsigned bBase = aBase + A_PB;

        // ---- load fragments for BOTH k-steps, then issue all MMAs ----
        unsigned bh[2][8][2], ah[2][4][4];
        #pragma unroll
        for (int kh = 0; kh < 2; kh++) {
            const int ks = kh * 16;
            #pragma unroll
            for (int nip = 0; nip < 4; nip++) {
                const int nf = wn + nip * 16;
                unsigned off;
                if (B_T) {
                    off = bBase + (ks + la7 + 8 * la_b3) * 272 + (nf + 8 * la_hi4) * 2;
                } else {
                    off = bBase + (nf + la7 + 8 * la_hi4) * 80 + (ks + 8 * la_b3) * 2;
                }
                unsigned r[4];
                ldsm4<B_T>(r, off);
                bh[kh][nip*2][0] = r[0]; bh[kh][nip*2][1] = r[1];
                bh[kh][nip*2+1][0] = r[2]; bh[kh][nip*2+1][1] = r[3];
            }
            #pragma unroll
            for (int mi = 0; mi < 4; mi++) {
                const int mf = wm + mi * 16;
                unsigned off;
                if (A_T) {
                    off = aBase + (ks + la7 + 8 * la_hi4) * 272 + (mf + 8 * la_b3) * 2;
                } else {
                    off = aBase + (mf + la15) * 80 + (ks + 8 * la_hi4) * 2;
                }
                ldsm4<A_T>(ah[kh][mi], off);
            }
        }
        #pragma unroll
        for (int kh = 0; kh < 2; kh++)
            #pragma unroll
            for (int mi = 0; mi < 4; mi++)
                #pragma unroll
                for (int ni = 0; ni < 8; ni++)
                    mma_f16(acc[mi][ni], ah[kh][mi], bh[kh][ni]);
    }

    // ---- epilogue ----
    #pragma unroll
    for (int mi = 0; mi < 4; mi++) {
        #pragma unroll
        for (int half = 0; half < 2; half++) {
            const int row = m0 + wm + mi * 16 + gid + half * 8;
            const float bv = (OUTM == 1 || OUTM == 2) ? bias[row] : 0.f;
            #pragma unroll
            for (int ni = 0; ni < 8; ni++) {
                const int col = n0 + wn + ni * 8 + tid4 * 2;
                float v0 = acc[mi][ni][half * 2 + 0] * alpha + bv;
                float v1 = acc[mi][ni][half * 2 + 1] * alpha + bv;
                const size_t off = (size_t)row * N + col;
                if (OUTM == 0) {
                    *(float2*)&C[off] = make_float2(v0, v1);
                } else if (OUTM == 1) {
                    const float* rp = res + off;
                    *(float2*)&C[off] = make_float2(v0 + rp[0], v1 + rp[1]);
                } else {
                    *(__half2*)&Ch[off] = __floats2half2_rn(v0, v1);
                }
            }
        }
    }
}

// ---------------------------------------------------------------------------
// Row softmax over 1024 elements + fp16 output.
// ---------------------------------------------------------------------------
__global__ void softmax_k(const float* __restrict__ S) {
    const size_t row = blockIdx.x;
    const float4* p = (const float4*)(S + row * (size_t)NPIX);
    float4 v = p[threadIdx.x];

    __shared__ float sh[8];
    __shared__ float bcast;

    float mx = fmaxf(fmaxf(v.x, v.y), fmaxf(v.z, v.w));
    mx = warp_max(mx);
    if (!(threadIdx.x & 31)) sh[threadIdx.x >> 5] = mx;
    __syncthreads();
    if (threadIdx.x < 32) {
        float t = (threadIdx.x < 8) ? sh[threadIdx.x] : -1e30f;
        t = warp_max(t);
        if (!threadIdx.x) bcast = t;
    }
    __syncthreads();
    mx = bcast;
    __syncthreads();

    v.x = __expf(v.x - mx); v.y = __expf(v.y - mx);
    v.z = __expf(v.z - mx); v.w = __expf(v.w - mx);
    float s = v.x + v.y + v.z + v.w;
    s = warp_sum(s);
    if (!(threadIdx.x & 31)) sh[threadIdx.x >> 5] = s;
    __syncthreads();
    if (threadIdx.x < 32) {
        float t = (threadIdx.x < 8) ? sh[threadIdx.x] : 0.f;
        t = warp_sum(t);
        if (!threadIdx.x) bcast = t;
    }
    __syncthreads();
    const float inv = 1.f / bcast;
    const size_t i2 = row * (NPIX / 2) + threadIdx.x * 2;
    ((__half2*)g_attb)[i2 + 0] = __floats2half2_rn(v.x * inv, v.y * inv);
    ((__half2*)g_attb)[i2 + 1] = __floats2half2_rn(v.z * inv, v.w * inv);
}

// ---------------------------------------------------------------------------
// Launch
// ---------------------------------------------------------------------------
extern "C" void kernel_launch(void* const* d_in, const int* in_sizes, int n_in,
                              void* d_out, int out_size) {
    const float* x  = (const float*)d_in[0];
    const float* nw = (const float*)d_in[1];
    const float* nb = (const float*)d_in[2];
    const float* qw = (const float*)d_in[3];
    const float* qb = (const float*)d_in[4];
    const float* pw = (const float*)d_in[5];
    const float* pb = (const float*)d_in[6];
    float* out = (float*)d_out;

    __half *wq, *wp, *qk, *at, *ho;
    float* attn;
    cudaGetSymbolAddress((void**)&wq, g_wq);
    cudaGetSymbolAddress((void**)&wp, g_wp);
    cudaGetSymbolAddress((void**)&qk, g_qkvb);
    cudaGetSymbolAddress((void**)&at, g_attb);
    cudaGetSymbolAddress((void**)&ho, g_houtb);
    cudaGetSymbolAddress((void**)&attn, g_attn);
    __half* hb;
    cudaGetSymbolAddress((void**)&hb, g_hb);

    const size_t sH   = (size_t)CH * NPIX;
    const size_t sQKV = (size_t)3 * CH * NPIX;
    const size_t sAT  = (size_t)NPIX * NPIX;

    // 4-stage dynamic smem: A tile (A_T? 8704:10240) + B tile (same formula)
    const int SM_QKV = 4 * (10240 + 8704);   // 75776  (A=false, B_T=true)
    const int SM_SC  = 4 * (8704 + 8704);    // 69632  (A_T, B_T)
    const int SM_AV  = 4 * (10240 + 10240);  // 81920  (A=false, B=false)
    const int SM_PR  = SM_QKV;

    cudaFuncSetAttribute(gemm_h<false,true ,2>, cudaFuncAttributeMaxDynamicSharedMemorySize, SM_QKV);
    cudaFuncSetAttribute(gemm_h<true ,true ,0>, cudaFuncAttributeMaxDynamicSharedMemorySize, SM_SC);
    cudaFuncSetAttribute(gemm_h<false,false,3>, cudaFuncAttributeMaxDynamicSharedMemorySize, SM_AV);
    cudaFuncSetAttribute(gemm_h<false,true ,1>, cudaFuncAttributeMaxDynamicSharedMemorySize, SM_PR);

    // 0) round weights to fp16
    wround_k<<<(3*CH*CH)/(4*256), 256>>>(qw, wq);
    wround_k<<<(CH*CH)/(4*256), 256>>>(pw, wp);

    // 1) fused GroupNorm (fp16 h)
    gn_fused_k<<<BATCH * NGRP, 256>>>(x, nw, nb);

    // 2) QKV = qkv_w @ h + qkv_b  (M=1536,N=1024,K=512)  A:[M][K], B:[K][N]
    gemm_h<false,true,2><<<dim3(8,12,BATCH), 128, SM_QKV>>>(
        wq, hb, nullptr, qk, qb, nullptr,
        3*CH, NPIX, CH, CH, NPIX, 0, sH, sQKV, 1.f);

    // 3) scores[n][m] = scale * sum_c q[c][n] k[c][m]  (M=N=1024,K=512)
    const float scale = 0.044194173824159216f;
    gemm_h<true,true,0><<<dim3(8,8,BATCH), 128, SM_SC>>>(
        qk, qk + sH, attn, nullptr, nullptr, nullptr,
        NPIX, NPIX, CH, NPIX, NPIX, sQKV, sQKV, sAT, scale);

    // 4) softmax rows (fp16 out)
    softmax_k<<<BATCH * NPIX, 256>>>(attn);

    // 5) hout[c][n] = sum_m v[c][m] attn[n][m]  (M=512,N=1024,K=1024)
    gemm_h<false,false,3><<<dim3(8,4,BATCH), 128, SM_AV>>>(
        qk + 2*sH, at, nullptr, ho, nullptr, nullptr,
        CH, NPIX, NPIX, NPIX, NPIX, sQKV, sAT, sH, 1.f);

    // 6) out = x + proj_w @ hout + proj_b  (M=512,N=1024,K=512)
    gemm_h<false,true,1><<<dim3(8,4,BATCH), 128, SM_PR>>>(
        wp, ho, out, nullptr, pb, x,
        CH, NPIX, CH, CH, NPIX, 0, sH, sH, 1.f);
}